// round 1
// baseline (speedup 1.0000x reference)
#include <cuda_runtime.h>
#include <math.h>

#define NN 8192
#define DD 256
#define FF 128
#define BB 4096
#define BM 16
#define BN 64

// ---------------- device scratch (static globals: no allocation) ----------------
__device__ float d_Wh[NN * FF];      // Wh = embedding @ W      [N][F]
__device__ float d_WhT[FF * NN];     // Wh transposed           [F][N]
__device__ float d_Hout[NN * FF];    // normalized elu(att@Wh)  [N][F] (only needed rows written)
__device__ int   d_flags[NN];
__device__ int   d_list[NN];
__device__ int   d_count;

// ---------------- tiny setup kernels ----------------
__global__ void k_init() {
    int i = blockIdx.x * blockDim.x + threadIdx.x;
    if (i < NN) d_flags[i] = 0;
    if (i == 0) d_count = 0;
}
__global__ void k_mark(const int* __restrict__ x) {
    int i = blockIdx.x * blockDim.x + threadIdx.x;
    if (i < BB) d_flags[x[i]] = 1;
}
__global__ void k_compact() {
    int i = blockIdx.x * blockDim.x + threadIdx.x;
    if (i < NN && d_flags[i]) {
        int p = atomicAdd(&d_count, 1);
        d_list[p] = i;
    }
}

// ---------------- Wh = embedding @ W  (8192x256 @ 256x128), also writes Wh^T ----------------
__global__ __launch_bounds__(256) void k_whgemm(const float* __restrict__ emb,
                                                const float* __restrict__ W) {
    __shared__ float At[32][68];   // A tile transposed: At[k][m]
    __shared__ float Bs[32][128];  // B tile: Bs[k][f]
    int tid = threadIdx.x, tx = tid & 31, ty = tid >> 5;  // ty in 0..7
    int row0 = blockIdx.x * 64;
    float acc[8][4];
#pragma unroll
    for (int r = 0; r < 8; r++)
#pragma unroll
        for (int c = 0; c < 4; c++) acc[r][c] = 0.f;

    for (int k0 = 0; k0 < DD; k0 += 32) {
#pragma unroll
        for (int it = 0; it < 2; it++) {
            int id = it * 256 + tid;
            int r = id >> 3;
            int c4 = (id & 7) * 4;
            float4 v = *(const float4*)&emb[(row0 + r) * DD + k0 + c4];
            At[c4 + 0][r] = v.x; At[c4 + 1][r] = v.y;
            At[c4 + 2][r] = v.z; At[c4 + 3][r] = v.w;
        }
#pragma unroll
        for (int it = 0; it < 4; it++) {
            int id = it * 256 + tid;
            int r = id >> 5;
            int c4 = (id & 31) * 4;
            *(float4*)&Bs[r][c4] = *(const float4*)&W[(k0 + r) * FF + c4];
        }
        __syncthreads();
#pragma unroll
        for (int k = 0; k < 32; k++) {
            float4 a0 = *(const float4*)&At[k][8 * ty];
            float4 a1 = *(const float4*)&At[k][8 * ty + 4];
            float4 b  = *(const float4*)&Bs[k][4 * tx];
            float av[8] = {a0.x, a0.y, a0.z, a0.w, a1.x, a1.y, a1.z, a1.w};
            float bv[4] = {b.x, b.y, b.z, b.w};
#pragma unroll
            for (int r = 0; r < 8; r++)
#pragma unroll
                for (int c = 0; c < 4; c++) acc[r][c] += av[r] * bv[c];
        }
        __syncthreads();
    }
#pragma unroll
    for (int r = 0; r < 8; r++) {
        int row = row0 + 8 * ty + r;
        float4 v = make_float4(acc[r][0], acc[r][1], acc[r][2], acc[r][3]);
        *(float4*)&d_Wh[row * FF + 4 * tx] = v;
        d_WhT[(4 * tx + 0) * NN + row] = v.x;
        d_WhT[(4 * tx + 1) * NN + row] = v.y;
        d_WhT[(4 * tx + 2) * NN + row] = v.z;
        d_WhT[(4 * tx + 3) * NN + row] = v.w;
    }
}

// ---------------- fused masked attention (flash-style), only needed rows ----------------
struct AttnSmem {
    float whiT[FF][20];   // Wh_I transposed: [f][m], pad 16->20
    float whJ[BN][132];   // Wh_J:            [j][f], pad 128->132
    float whJT[FF][BN];   // Wh_J transposed: [f][j]
    float pt[BN][20];     // P transposed:    [j][m], pad 16->20
    int rows[BM];
    int valid[BM];
};

__global__ __launch_bounds__(128, 2) void k_attn(const int* __restrict__ adj) {
    extern __shared__ char smraw[];
    AttnSmem& sm = *(AttnSmem*)smraw;
    int tid = threadIdx.x, tx = tid & 31, ty = tid >> 5;  // ty in 0..3 (one warp per 4 rows)
    int cnt = d_count;
    int ntiles = (cnt + BM - 1) / BM;

    for (int tile = blockIdx.x; tile < ntiles; tile += gridDim.x) {
        if (tid < BM) {
            int r = tile * BM + tid;
            int row = (r < cnt) ? d_list[r] : d_list[cnt - 1];
            sm.rows[tid] = row;
            sm.valid[tid] = (r < cnt) ? 1 : 0;
        }
        __syncthreads();
        // load Wh_I (16 x 128) transposed into smem
#pragma unroll
        for (int it = 0; it < 4; it++) {
            int id = it * 128 + tid;
            int m = id >> 5;
            int c4 = (id & 31) * 4;
            float4 v = *(const float4*)&d_Wh[sm.rows[m] * FF + c4];
            sm.whiT[c4 + 0][m] = v.x; sm.whiT[c4 + 1][m] = v.y;
            sm.whiT[c4 + 2][m] = v.z; sm.whiT[c4 + 3][m] = v.w;
        }
        float mrow[4], lrow[4], O[4][4];
#pragma unroll
        for (int r = 0; r < 4; r++) {
            mrow[r] = -1e30f; lrow[r] = 0.f;
#pragma unroll
            for (int c = 0; c < 4; c++) O[r][c] = 0.f;
        }
        long arow[4];
#pragma unroll
        for (int r = 0; r < 4; r++) arow[r] = (long)sm.rows[4 * ty + r] * NN;
        __syncthreads();

        for (int j0 = 0; j0 < NN; j0 += BN) {
            // adjacency bits for this thread's S elements (4 rows x 2 cols)
            int2 am[4];
#pragma unroll
            for (int r = 0; r < 4; r++)
                am[r] = *(const int2*)&adj[arow[r] + j0 + 2 * tx];
            // load Wh_J tile both layouts (conflict-free: straight rows from Wh and Wh^T)
#pragma unroll
            for (int it = 0; it < 16; it++) {
                int id = it * 128 + tid;
                int jr = id >> 5;
                int c4 = (id & 31) * 4;
                *(float4*)&sm.whJ[jr][c4] = *(const float4*)&d_Wh[(j0 + jr) * FF + c4];
            }
#pragma unroll
            for (int it = 0; it < 16; it++) {
                int id = it * 128 + tid;
                int f = id >> 4;
                int c4 = (id & 15) * 4;
                *(float4*)&sm.whJT[f][c4] = *(const float4*)&d_WhT[f * NN + j0 + c4];
            }
            __syncthreads();
            // GEMM1: S[4m][2j] = Wh_I . Wh_J^T  (k = feature)
            float S[4][2];
#pragma unroll
            for (int r = 0; r < 4; r++) { S[r][0] = 0.f; S[r][1] = 0.f; }
#pragma unroll 8
            for (int k = 0; k < FF; k++) {
                float4 a = *(const float4*)&sm.whiT[k][4 * ty];
                float2 b = *(const float2*)&sm.whJT[k][2 * tx];
                S[0][0] += a.x * b.x; S[0][1] += a.x * b.y;
                S[1][0] += a.y * b.x; S[1][1] += a.y * b.y;
                S[2][0] += a.z * b.x; S[2][1] += a.z * b.y;
                S[3][0] += a.w * b.x; S[3][1] += a.w * b.y;
            }
            // masked online softmax
#pragma unroll
            for (int r = 0; r < 4; r++) {
                float s0 = am[r].x ? S[r][0] : -1e30f;
                float s1 = am[r].y ? S[r][1] : -1e30f;
                float mx = fmaxf(s0, s1);
#pragma unroll
                for (int o = 16; o; o >>= 1)
                    mx = fmaxf(mx, __shfl_xor_sync(0xffffffffu, mx, o));
                if (mx > mrow[r]) {  // warp-uniform branch
                    float sc = __expf(mrow[r] - mx);
                    lrow[r] *= sc;
#pragma unroll
                    for (int c = 0; c < 4; c++) O[r][c] *= sc;
                    mrow[r] = mx;
                }
                float p0 = am[r].x ? __expf(s0 - mrow[r]) : 0.f;
                float p1 = am[r].y ? __expf(s1 - mrow[r]) : 0.f;
                lrow[r] += p0 + p1;
                sm.pt[2 * tx + 0][4 * ty + r] = p0;
                sm.pt[2 * tx + 1][4 * ty + r] = p1;
            }
            __syncthreads();
            // GEMM2: O[4m][4f] += P . Wh_J  (k = j)
#pragma unroll 8
            for (int k = 0; k < BN; k++) {
                float4 p = *(const float4*)&sm.pt[k][4 * ty];
                float4 b = *(const float4*)&sm.whJ[k][4 * tx];
                float pv[4] = {p.x, p.y, p.z, p.w};
                float bv[4] = {b.x, b.y, b.z, b.w};
#pragma unroll
                for (int r = 0; r < 4; r++)
#pragma unroll
                    for (int c = 0; c < 4; c++) O[r][c] += pv[r] * bv[c];
            }
            __syncthreads();
        }
        // epilogue: divide by l, elu, L2-normalize per row, write
#pragma unroll
        for (int r = 0; r < 4; r++) {
            float l = lrow[r];
#pragma unroll
            for (int o = 16; o; o >>= 1) l += __shfl_xor_sync(0xffffffffu, l, o);
            float inv = 1.f / l;
            float h[4];
            float ssq = 0.f;
#pragma unroll
            for (int c = 0; c < 4; c++) {
                float v = O[r][c] * inv;
                v = (v > 0.f) ? v : expm1f(v);
                h[c] = v;
                ssq += v * v;
            }
#pragma unroll
            for (int o = 16; o; o >>= 1) ssq += __shfl_xor_sync(0xffffffffu, ssq, o);
            float innrm = 1.f / fmaxf(sqrtf(ssq), 1e-12f);
            if (sm.valid[4 * ty + r]) {
                float4 ov = make_float4(h[0] * innrm, h[1] * innrm, h[2] * innrm, h[3] * innrm);
                *(float4*)&d_Hout[sm.rows[4 * ty + r] * FF + 4 * tx] = ov;
            }
        }
        __syncthreads();  // protect sm.rows/valid before next tile overwrites
    }
}

// ---------------- output gather ----------------
__global__ void k_gather(const int* __restrict__ x, float* __restrict__ out) {
    int id = blockIdx.x * blockDim.x + threadIdx.x;
    if (id < BB * 32) {
        int b = id >> 5;
        int c4 = (id & 31) * 4;
        *(float4*)&out[b * FF + c4] = *(const float4*)&d_Hout[(long)x[b] * FF + c4];
    }
}

extern "C" void kernel_launch(void* const* d_in, const int* in_sizes, int n_in,
                              void* d_out, int out_size) {
    const int*   x   = (const int*)d_in[0];
    const int*   adj = (const int*)d_in[1];
    const float* emb = (const float*)d_in[2];
    const float* W   = (const float*)d_in[3];
    float* out = (float*)d_out;

    cudaFuncSetAttribute(k_attn, cudaFuncAttributeMaxDynamicSharedMemorySize,
                         (int)sizeof(AttnSmem));

    k_init<<<(NN + 255) / 256, 256>>>();
    k_mark<<<(BB + 255) / 256, 256>>>(x);
    k_compact<<<(NN + 255) / 256, 256>>>();
    k_whgemm<<<NN / 64, 256>>>(emb, W);
    k_attn<<<256, 128, sizeof(AttnSmem)>>>(adj);
    k_gather<<<(BB * 32 + 255) / 256, 256>>>(x, out);
}

// round 2
// speedup vs baseline: 1.0494x; 1.0494x over previous
#include <cuda_runtime.h>
#include <math.h>

#define NN 8192
#define DD 256
#define FF 128
#define BB 4096
#define BM 16
#define BN 64

// ---------------- device scratch (static globals: no allocation) ----------------
__device__ float d_Wh[NN * FF];      // Wh = embedding @ W      [N][F]
__device__ float d_WhT[FF * NN];     // Wh transposed           [F][N]
__device__ float d_Hout[NN * FF];    // normalized elu(att@Wh)  [N][F] (only needed rows written)
__device__ int   d_flags[NN];
__device__ int   d_list[NN];
__device__ int   d_count;

// ---------------- tiny setup kernels ----------------
__global__ void k_init() {
    int i = blockIdx.x * blockDim.x + threadIdx.x;
    if (i < NN) d_flags[i] = 0;
    if (i == 0) d_count = 0;
}
__global__ void k_mark(const int* __restrict__ x) {
    int i = blockIdx.x * blockDim.x + threadIdx.x;
    if (i < BB) d_flags[x[i]] = 1;
}
__global__ void k_compact() {
    int i = blockIdx.x * blockDim.x + threadIdx.x;
    if (i < NN && d_flags[i]) {
        int p = atomicAdd(&d_count, 1);
        d_list[p] = i;
    }
}

// ---------------- Wh = embedding @ W  (8192x256 @ 256x128), also writes Wh^T ----------------
__global__ __launch_bounds__(256) void k_whgemm(const float* __restrict__ emb,
                                                const float* __restrict__ W) {
    __shared__ float At[32][68];   // A tile transposed: At[k][m]
    __shared__ float Bs[32][128];  // B tile: Bs[k][f]
    int tid = threadIdx.x, tx = tid & 31, ty = tid >> 5;  // ty in 0..7
    int row0 = blockIdx.x * 64;
    float acc[8][4];
#pragma unroll
    for (int r = 0; r < 8; r++)
#pragma unroll
        for (int c = 0; c < 4; c++) acc[r][c] = 0.f;

    for (int k0 = 0; k0 < DD; k0 += 32) {
#pragma unroll
        for (int it = 0; it < 2; it++) {
            int id = it * 256 + tid;
            int r = id >> 3;
            int c4 = (id & 7) * 4;
            float4 v = *(const float4*)&emb[(row0 + r) * DD + k0 + c4];
            At[c4 + 0][r] = v.x; At[c4 + 1][r] = v.y;
            At[c4 + 2][r] = v.z; At[c4 + 3][r] = v.w;
        }
#pragma unroll
        for (int it = 0; it < 4; it++) {
            int id = it * 256 + tid;
            int r = id >> 5;
            int c4 = (id & 31) * 4;
            *(float4*)&Bs[r][c4] = *(const float4*)&W[(k0 + r) * FF + c4];
        }
        __syncthreads();
#pragma unroll
        for (int k = 0; k < 32; k++) {
            float4 a0 = *(const float4*)&At[k][8 * ty];
            float4 a1 = *(const float4*)&At[k][8 * ty + 4];
            float4 b  = *(const float4*)&Bs[k][4 * tx];
            float av[8] = {a0.x, a0.y, a0.z, a0.w, a1.x, a1.y, a1.z, a1.w};
            float bv[4] = {b.x, b.y, b.z, b.w};
#pragma unroll
            for (int r = 0; r < 8; r++)
#pragma unroll
                for (int c = 0; c < 4; c++) acc[r][c] += av[r] * bv[c];
        }
        __syncthreads();
    }
#pragma unroll
    for (int r = 0; r < 8; r++) {
        int row = row0 + 8 * ty + r;
        float4 v = make_float4(acc[r][0], acc[r][1], acc[r][2], acc[r][3]);
        *(float4*)&d_Wh[row * FF + 4 * tx] = v;
        d_WhT[(4 * tx + 0) * NN + row] = v.x;
        d_WhT[(4 * tx + 1) * NN + row] = v.y;
        d_WhT[(4 * tx + 2) * NN + row] = v.z;
        d_WhT[(4 * tx + 3) * NN + row] = v.w;
    }
}

// ---------------- fused masked attention (flash-style), only needed rows ----------------
struct AttnSmem {
    float whiT[FF][20];   // Wh_I transposed: [f][m], pad 16->20
    float whJ[BN][132];   // Wh_J:            [j][f], pad 128->132
    float whJT[FF][BN];   // Wh_J transposed: [f][j]
    float pt[BN][20];     // P transposed:    [j][m], pad 16->20
    int rows[BM];
    int valid[BM];
};

__global__ __launch_bounds__(128, 2) void k_attn(const int* __restrict__ adj) {
    extern __shared__ char smraw[];
    AttnSmem& sm = *(AttnSmem*)smraw;
    int tid = threadIdx.x, tx = tid & 31, ty = tid >> 5;  // ty in 0..3 (one warp per 4 rows)
    int cnt = d_count;
    int ntiles = (cnt + BM - 1) / BM;

    for (int tile = blockIdx.x; tile < ntiles; tile += gridDim.x) {
        if (tid < BM) {
            int r = tile * BM + tid;
            int row = (r < cnt) ? d_list[r] : d_list[cnt - 1];
            sm.rows[tid] = row;
            sm.valid[tid] = (r < cnt) ? 1 : 0;
        }
        __syncthreads();
        // load Wh_I (16 x 128) transposed into smem
#pragma unroll
        for (int it = 0; it < 4; it++) {
            int id = it * 128 + tid;
            int m = id >> 5;
            int c4 = (id & 31) * 4;
            float4 v = *(const float4*)&d_Wh[sm.rows[m] * FF + c4];
            sm.whiT[c4 + 0][m] = v.x; sm.whiT[c4 + 1][m] = v.y;
            sm.whiT[c4 + 2][m] = v.z; sm.whiT[c4 + 3][m] = v.w;
        }
        float mrow[4], lrow[4], O[4][4];
#pragma unroll
        for (int r = 0; r < 4; r++) {
            mrow[r] = -1e30f; lrow[r] = 0.f;
#pragma unroll
            for (int c = 0; c < 4; c++) O[r][c] = 0.f;
        }
        long arow[4];
#pragma unroll
        for (int r = 0; r < 4; r++) arow[r] = (long)sm.rows[4 * ty + r] * NN;
        __syncthreads();

        for (int j0 = 0; j0 < NN; j0 += BN) {
            // adjacency bits for this thread's S elements (4 rows x 2 cols)
            int2 am[4];
#pragma unroll
            for (int r = 0; r < 4; r++)
                am[r] = *(const int2*)&adj[arow[r] + j0 + 2 * tx];
            // load Wh_J tile both layouts (conflict-free: straight rows from Wh and Wh^T)
#pragma unroll
            for (int it = 0; it < 16; it++) {
                int id = it * 128 + tid;
                int jr = id >> 5;
                int c4 = (id & 31) * 4;
                *(float4*)&sm.whJ[jr][c4] = *(const float4*)&d_Wh[(j0 + jr) * FF + c4];
            }
#pragma unroll
            for (int it = 0; it < 16; it++) {
                int id = it * 128 + tid;
                int f = id >> 4;
                int c4 = (id & 15) * 4;
                *(float4*)&sm.whJT[f][c4] = *(const float4*)&d_WhT[f * NN + j0 + c4];
            }
            __syncthreads();
            // GEMM1: S[4m][2j] = Wh_I . Wh_J^T  (k = feature)
            float S[4][2];
#pragma unroll
            for (int r = 0; r < 4; r++) { S[r][0] = 0.f; S[r][1] = 0.f; }
#pragma unroll 8
            for (int k = 0; k < FF; k++) {
                float4 a = *(const float4*)&sm.whiT[k][4 * ty];
                float2 b = *(const float2*)&sm.whJT[k][2 * tx];
                S[0][0] += a.x * b.x; S[0][1] += a.x * b.y;
                S[1][0] += a.y * b.x; S[1][1] += a.y * b.y;
                S[2][0] += a.z * b.x; S[2][1] += a.z * b.y;
                S[3][0] += a.w * b.x; S[3][1] += a.w * b.y;
            }
            // masked online softmax
#pragma unroll
            for (int r = 0; r < 4; r++) {
                float s0 = am[r].x ? S[r][0] : -1e30f;
                float s1 = am[r].y ? S[r][1] : -1e30f;
                float mx = fmaxf(s0, s1);
#pragma unroll
                for (int o = 16; o; o >>= 1)
                    mx = fmaxf(mx, __shfl_xor_sync(0xffffffffu, mx, o));
                if (mx > mrow[r]) {  // warp-uniform branch
                    float sc = __expf(mrow[r] - mx);
                    lrow[r] *= sc;
#pragma unroll
                    for (int c = 0; c < 4; c++) O[r][c] *= sc;
                    mrow[r] = mx;
                }
                float p0 = am[r].x ? __expf(s0 - mrow[r]) : 0.f;
                float p1 = am[r].y ? __expf(s1 - mrow[r]) : 0.f;
                lrow[r] += p0 + p1;
                sm.pt[2 * tx + 0][4 * ty + r] = p0;
                sm.pt[2 * tx + 1][4 * ty + r] = p1;
            }
            __syncthreads();
            // GEMM2: O[4m][4f] += P . Wh_J  (k = j)
#pragma unroll 8
            for (int k = 0; k < BN; k++) {
                float4 p = *(const float4*)&sm.pt[k][4 * ty];
                float4 b = *(const float4*)&sm.whJ[k][4 * tx];
                float pv[4] = {p.x, p.y, p.z, p.w};
                float bv[4] = {b.x, b.y, b.z, b.w};
#pragma unroll
                for (int r = 0; r < 4; r++)
#pragma unroll
                    for (int c = 0; c < 4; c++) O[r][c] += pv[r] * bv[c];
            }
            __syncthreads();
        }
        // epilogue: divide by l, elu, L2-normalize per row, write
#pragma unroll
        for (int r = 0; r < 4; r++) {
            float l = lrow[r];
#pragma unroll
            for (int o = 16; o; o >>= 1) l += __shfl_xor_sync(0xffffffffu, l, o);
            float inv = 1.f / l;
            float h[4];
            float ssq = 0.f;
#pragma unroll
            for (int c = 0; c < 4; c++) {
                float v = O[r][c] * inv;
                v = (v > 0.f) ? v : expm1f(v);
                h[c] = v;
                ssq += v * v;
            }
#pragma unroll
            for (int o = 16; o; o >>= 1) ssq += __shfl_xor_sync(0xffffffffu, ssq, o);
            float innrm = 1.f / fmaxf(sqrtf(ssq), 1e-12f);
            if (sm.valid[4 * ty + r]) {
                float4 ov = make_float4(h[0] * innrm, h[1] * innrm, h[2] * innrm, h[3] * innrm);
                *(float4*)&d_Hout[sm.rows[4 * ty + r] * FF + 4 * tx] = ov;
            }
        }
        __syncthreads();  // protect sm.rows/valid before next tile overwrites
    }
}

// ---------------- output gather ----------------
__global__ void k_gather(const int* __restrict__ x, float* __restrict__ out) {
    int id = blockIdx.x * blockDim.x + threadIdx.x;
    if (id < BB * 32) {
        int b = id >> 5;
        int c4 = (id & 31) * 4;
        *(float4*)&out[b * FF + c4] = *(const float4*)&d_Hout[(long)x[b] * FF + c4];
    }
}

extern "C" void kernel_launch(void* const* d_in, const int* in_sizes, int n_in,
                              void* d_out, int out_size) {
    const int*   x   = (const int*)d_in[0];
    const int*   adj = (const int*)d_in[1];
    const float* emb = (const float*)d_in[2];
    const float* W   = (const float*)d_in[3];
    float* out = (float*)d_out;

    cudaFuncSetAttribute(k_attn, cudaFuncAttributeMaxDynamicSharedMemorySize,
                         (int)sizeof(AttnSmem));

    k_init<<<(NN + 255) / 256, 256>>>();
    k_mark<<<(BB + 255) / 256, 256>>>(x);
    k_compact<<<(NN + 255) / 256, 256>>>();
    k_whgemm<<<NN / 64, 256>>>(emb, W);
    k_attn<<<256, 128, sizeof(AttnSmem)>>>(adj);
    k_gather<<<(BB * 32 + 255) / 256, 256>>>(x, out);
}

// round 3
// speedup vs baseline: 1.6455x; 1.5681x over previous
#include <cuda_runtime.h>
#include <math.h>

#define NN 8192
#define DD 256
#define FF 128
#define BB 4096

#define BM 64
#define BN 64
#define JSPLIT 16
#define JCHUNK (NN / JSPLIT)        // 512
#define JITERS (JCHUNK / BN)        // 8
#define MAXTILES (NN / BM)          // 128
#define MAXUNITS (MAXTILES * JSPLIT)// 2048
#define ATTN_GRID 296

typedef unsigned long long ull;

// ---------------- device scratch ----------------
__device__ float d_Wh[NN * FF];
__device__ float d_WhT[FF * NN];
__device__ float d_Hout[NN * FF];
__device__ int   d_flags[NN];
__device__ int   d_list[NN];
__device__ int   d_count;
__device__ float d_pm[MAXUNITS * BM];
__device__ float d_pl[MAXUNITS * BM];
__device__ float d_pO[(size_t)MAXUNITS * BM * FF];   // 64 MB partial O

// ---------------- f32x2 helpers ----------------
__device__ __forceinline__ void ffma2(ull& d, ull a, ull b) {
    asm("fma.rn.f32x2 %0, %1, %2, %0;" : "+l"(d) : "l"(a), "l"(b));
}
__device__ __forceinline__ void mul2(ull& d, ull s) {
    asm("mul.rn.f32x2 %0, %0, %1;" : "+l"(d) : "l"(s));
}
__device__ __forceinline__ ull pack2(float lo, float hi) {
    ull r; asm("mov.b64 %0, {%1, %2};" : "=l"(r) : "f"(lo), "f"(hi)); return r;
}
__device__ __forceinline__ float2 unpack2(ull v) {
    float2 f; asm("mov.b64 {%0, %1}, %2;" : "=f"(f.x), "=f"(f.y) : "l"(v)); return f;
}

// ---------------- tiny setup kernels ----------------
__global__ void k_init() {
    int i = blockIdx.x * blockDim.x + threadIdx.x;
    if (i < NN) d_flags[i] = 0;
    if (i == 0) d_count = 0;
}
__global__ void k_mark(const int* __restrict__ x) {
    int i = blockIdx.x * blockDim.x + threadIdx.x;
    if (i < BB) d_flags[x[i]] = 1;
}
__global__ void k_compact() {
    int i = blockIdx.x * blockDim.x + threadIdx.x;
    if (i < NN && d_flags[i]) {
        int p = atomicAdd(&d_count, 1);
        d_list[p] = i;
    }
}

// ---------------- Wh = embedding @ W, plus Wh^T ----------------
__global__ __launch_bounds__(256) void k_whgemm(const float* __restrict__ emb,
                                                const float* __restrict__ W) {
    __shared__ float At[32][68];
    __shared__ float Bs[32][128];
    int tid = threadIdx.x, tx = tid & 31, ty = tid >> 5;
    int row0 = blockIdx.x * 64;
    float acc[8][4];
#pragma unroll
    for (int r = 0; r < 8; r++)
#pragma unroll
        for (int c = 0; c < 4; c++) acc[r][c] = 0.f;

    for (int k0 = 0; k0 < DD; k0 += 32) {
#pragma unroll
        for (int it = 0; it < 2; it++) {
            int id = it * 256 + tid;
            int r = id >> 3;
            int c4 = (id & 7) * 4;
            float4 v = *(const float4*)&emb[(row0 + r) * DD + k0 + c4];
            At[c4 + 0][r] = v.x; At[c4 + 1][r] = v.y;
            At[c4 + 2][r] = v.z; At[c4 + 3][r] = v.w;
        }
#pragma unroll
        for (int it = 0; it < 4; it++) {
            int id = it * 256 + tid;
            int r = id >> 5;
            int c4 = (id & 31) * 4;
            *(float4*)&Bs[r][c4] = *(const float4*)&W[(k0 + r) * FF + c4];
        }
        __syncthreads();
#pragma unroll
        for (int k = 0; k < 32; k++) {
            float4 a0 = *(const float4*)&At[k][8 * ty];
            float4 a1 = *(const float4*)&At[k][8 * ty + 4];
            float4 b  = *(const float4*)&Bs[k][4 * tx];
            float av[8] = {a0.x, a0.y, a0.z, a0.w, a1.x, a1.y, a1.z, a1.w};
            float bv[4] = {b.x, b.y, b.z, b.w};
#pragma unroll
            for (int r = 0; r < 8; r++)
#pragma unroll
                for (int c = 0; c < 4; c++) acc[r][c] += av[r] * bv[c];
        }
        __syncthreads();
    }
#pragma unroll
    for (int r = 0; r < 8; r++) {
        int row = row0 + 8 * ty + r;
        float4 v = make_float4(acc[r][0], acc[r][1], acc[r][2], acc[r][3]);
        *(float4*)&d_Wh[row * FF + 4 * tx] = v;
        d_WhT[(4 * tx + 0) * NN + row] = v.x;
        d_WhT[(4 * tx + 1) * NN + row] = v.y;
        d_WhT[(4 * tx + 2) * NN + row] = v.z;
        d_WhT[(4 * tx + 3) * NN + row] = v.w;
    }
}

// ---------------- fused masked attention: split-KV partials ----------------
// Smem = 3*32KB + 16KB = 114688 B exactly (14 x 8KB granules) -> 2 CTAs/SM.
struct AttnSmem {
    float whiT[FF][BM];   // Wh_I^T : [f][m]
    float whJT[FF][BN];   // Wh_J^T : [f][j]   (GEMM1 B)
    float whJ[BN][FF];    // Wh_J   : [j][f]   (GEMM2 B)
    float pt[BM][BN];     // P      : [m][j]
};

__global__ __launch_bounds__(256, 2) void k_attn(const int* __restrict__ adj) {
    extern __shared__ char smraw[];
    AttnSmem& sm = *(AttnSmem*)smraw;
    const int tid = threadIdx.x;
    const int i  = tid >> 4;   // 0..15 : rows 4i..4i+3
    const int jj = tid & 15;   // 0..15 : GEMM1 cols 4jj.., GEMM2 f 8jj..
    const int cnt = d_count;
    const int ntiles = (cnt + BM - 1) / BM;
    const int nunits = ntiles * JSPLIT;

    for (int u = blockIdx.x; u < nunits; u += gridDim.x) {
        const int tile  = u / JSPLIT;
        const int slice = u - tile * JSPLIT;
        const int jbase0 = slice * JCHUNK;

        __syncthreads();  // previous unit fully done before overwriting whiT

        // prologue: gather whiT[f][m] from d_WhT (conflict-free STS)
#pragma unroll
        for (int s = 0; s < 8; s++) {
            int id = s * 256 + tid;
            int f = id >> 4;
            int m4 = (id & 15) * 4;
            float v[4];
#pragma unroll
            for (int q = 0; q < 4; q++) {
                int ridx = tile * BM + m4 + q;
                int row = d_list[ridx < cnt ? ridx : cnt - 1];
                v[q] = d_WhT[(size_t)f * NN + row];
            }
            *(float4*)&sm.whiT[f][m4] = make_float4(v[0], v[1], v[2], v[3]);
        }
        size_t arow[4];
#pragma unroll
        for (int r = 0; r < 4; r++) {
            int ridx = tile * BM + 4 * i + r;
            arow[r] = (size_t)d_list[ridx < cnt ? ridx : cnt - 1] * NN;
        }

        float mrow[4], lrow[4];
        ull O2[4][4];
#pragma unroll
        for (int r = 0; r < 4; r++) {
            mrow[r] = -1e30f; lrow[r] = 0.f;
#pragma unroll
            for (int c = 0; c < 4; c++) O2[r][c] = 0ULL;
        }

        for (int it = 0; it < JITERS; it++) {
            int j0 = jbase0 + it * BN;
            // adjacency bits (issued early; consumed after GEMM1)
            int4 am[4];
#pragma unroll
            for (int r = 0; r < 4; r++)
                am[r] = *(const int4*)&adj[arow[r] + j0 + 4 * jj];

            // load J tile both layouts
#pragma unroll
            for (int s = 0; s < 8; s++) {
                int id = s * 256 + tid;
                int f = id >> 4;
                int c4 = (id & 15) * 4;
                *(float4*)&sm.whJT[f][c4] =
                    *(const float4*)&d_WhT[(size_t)f * NN + j0 + c4];
            }
#pragma unroll
            for (int s = 0; s < 8; s++) {
                int id = s * 256 + tid;
                int jr = id >> 5;
                int c4 = (id & 31) * 4;
                *(float4*)&sm.whJ[jr][c4] =
                    *(const float4*)&d_Wh[(size_t)(j0 + jr) * FF + c4];
            }
            __syncthreads();

            // GEMM1: S[4m][4j] = Wh_I . Wh_J^T  (f32x2, j packed in lanes)
            ull S2[4][2];
#pragma unroll
            for (int r = 0; r < 4; r++) { S2[r][0] = 0ULL; S2[r][1] = 0ULL; }
#pragma unroll 4
            for (int k = 0; k < FF; k++) {
                float4 a4 = *(const float4*)&sm.whiT[k][4 * i];
                ulonglong2 b2 = *(const ulonglong2*)&sm.whJT[k][4 * jj];
                float af[4] = {a4.x, a4.y, a4.z, a4.w};
#pragma unroll
                for (int r = 0; r < 4; r++) {
                    ull ad = pack2(af[r], af[r]);
                    ffma2(S2[r][0], ad, b2.x);
                    ffma2(S2[r][1], ad, b2.y);
                }
            }

            // masked online softmax (16-lane row groups)
#pragma unroll
            for (int r = 0; r < 4; r++) {
                float2 s01 = unpack2(S2[r][0]);
                float2 s23 = unpack2(S2[r][1]);
                float s0 = am[r].x ? s01.x : -1e30f;
                float s1 = am[r].y ? s01.y : -1e30f;
                float s2 = am[r].z ? s23.x : -1e30f;
                float s3 = am[r].w ? s23.y : -1e30f;
                float mx = fmaxf(fmaxf(s0, s1), fmaxf(s2, s3));
#pragma unroll
                for (int o = 8; o; o >>= 1)
                    mx = fmaxf(mx, __shfl_xor_sync(0xffffffffu, mx, o));
                if (mx > mrow[r]) {
                    float sc = __expf(mrow[r] - mx);
                    lrow[r] *= sc;
                    ull scp = pack2(sc, sc);
                    mul2(O2[r][0], scp); mul2(O2[r][1], scp);
                    mul2(O2[r][2], scp); mul2(O2[r][3], scp);
                    mrow[r] = mx;
                }
                float p0 = am[r].x ? __expf(s0 - mrow[r]) : 0.f;
                float p1 = am[r].y ? __expf(s1 - mrow[r]) : 0.f;
                float p2 = am[r].z ? __expf(s2 - mrow[r]) : 0.f;
                float p3 = am[r].w ? __expf(s3 - mrow[r]) : 0.f;
                lrow[r] += (p0 + p1) + (p2 + p3);
                *(float4*)&sm.pt[4 * i + r][4 * jj] = make_float4(p0, p1, p2, p3);
            }
            __syncthreads();

            // GEMM2: O[4m][8f] += P . Wh_J  (f32x2, f packed in lanes)
#pragma unroll 2
            for (int k = 0; k < BN; k++) {
                ulonglong2 ba = *(const ulonglong2*)&sm.whJ[k][8 * jj];
                ulonglong2 bb = *(const ulonglong2*)&sm.whJ[k][8 * jj + 4];
#pragma unroll
                for (int r = 0; r < 4; r++) {
                    float pv = sm.pt[4 * i + r][k];
                    ull pd = pack2(pv, pv);
                    ffma2(O2[r][0], pd, ba.x);
                    ffma2(O2[r][1], pd, ba.y);
                    ffma2(O2[r][2], pd, bb.x);
                    ffma2(O2[r][3], pd, bb.y);
                }
            }
            __syncthreads();
        }

        // epilogue: write partial (m, l, O) for this (tile, slice)
#pragma unroll
        for (int r = 0; r < 4; r++) {
            float l = lrow[r];
#pragma unroll
            for (int o = 8; o; o >>= 1) l += __shfl_xor_sync(0xffffffffu, l, o);
            size_t pbase = ((size_t)u * BM + 4 * i + r) * FF + 8 * jj;
            float2 o0 = unpack2(O2[r][0]);
            float2 o1 = unpack2(O2[r][1]);
            float2 o2 = unpack2(O2[r][2]);
            float2 o3 = unpack2(O2[r][3]);
            *(float4*)&d_pO[pbase]     = make_float4(o0.x, o0.y, o1.x, o1.y);
            *(float4*)&d_pO[pbase + 4] = make_float4(o2.x, o2.y, o3.x, o3.y);
            if (jj == 0) {
                d_pm[u * BM + 4 * i + r] = mrow[r];
                d_pl[u * BM + 4 * i + r] = l;
            }
        }
    }
}

// ---------------- combine partials + elu + L2 normalize ----------------
__global__ __launch_bounds__(128) void k_reduce() {
    int rid = blockIdx.x;
    int cnt = d_count;
    if (rid >= cnt) return;
    int tile = rid / BM, mloc = rid - tile * BM;
    int f = threadIdx.x;
    int base = tile * JSPLIT;

    float M = -1e30f;
#pragma unroll
    for (int s = 0; s < JSPLIT; s++)
        M = fmaxf(M, d_pm[(base + s) * BM + mloc]);
    float L = 0.f, acc = 0.f;
#pragma unroll
    for (int s = 0; s < JSPLIT; s++) {
        float w = __expf(d_pm[(base + s) * BM + mloc] - M);
        L += w * d_pl[(base + s) * BM + mloc];
        acc += w * d_pO[((size_t)(base + s) * BM + mloc) * FF + f];
    }
    float v = acc / L;
    v = (v > 0.f) ? v : expm1f(v);

    __shared__ float red[4];
    float ssq = v * v;
#pragma unroll
    for (int o = 16; o; o >>= 1) ssq += __shfl_xor_sync(0xffffffffu, ssq, o);
    int lane = f & 31, w = f >> 5;
    if (lane == 0) red[w] = ssq;
    __syncthreads();
    ssq = red[0] + red[1] + red[2] + red[3];
    float inn = 1.f / fmaxf(sqrtf(ssq), 1e-12f);
    d_Hout[(size_t)d_list[rid] * FF + f] = v * inn;
}

// ---------------- output gather ----------------
__global__ void k_gather(const int* __restrict__ x, float* __restrict__ out) {
    int id = blockIdx.x * blockDim.x + threadIdx.x;
    if (id < BB * 32) {
        int b = id >> 5;
        int c4 = (id & 31) * 4;
        *(float4*)&out[b * FF + c4] = *(const float4*)&d_Hout[(size_t)x[b] * FF + c4];
    }
}

extern "C" void kernel_launch(void* const* d_in, const int* in_sizes, int n_in,
                              void* d_out, int out_size) {
    const int*   x   = (const int*)d_in[0];
    const int*   adj = (const int*)d_in[1];
    const float* emb = (const float*)d_in[2];
    const float* W   = (const float*)d_in[3];
    float* out = (float*)d_out;

    cudaFuncSetAttribute(k_attn, cudaFuncAttributeMaxDynamicSharedMemorySize,
                         (int)sizeof(AttnSmem));

    k_init<<<(NN + 255) / 256, 256>>>();
    k_mark<<<(BB + 255) / 256, 256>>>(x);
    k_compact<<<(NN + 255) / 256, 256>>>();
    k_whgemm<<<NN / 64, 256>>>(emb, W);
    k_attn<<<ATTN_GRID, 256, sizeof(AttnSmem)>>>(adj);
    k_reduce<<<NN, 128>>>();
    k_gather<<<(BB * 32 + 255) / 256, 256>>>(x, out);
}

// round 4
// speedup vs baseline: 1.6498x; 1.0026x over previous
#include <cuda_runtime.h>
#include <math.h>

#define NN 8192
#define DD 256
#define FF 128
#define BB 4096

#define BM 64
#define BN 64
#define JSPLIT 16
#define JCHUNK (NN / JSPLIT)        // 512
#define JITERS (JCHUNK / BN)        // 8
#define MAXTILES (NN / BM)          // 128
#define MAXUNITS (MAXTILES * JSPLIT)// 2048
#define ATTN_GRID 296

typedef unsigned long long ull;

// ---------------- device scratch ----------------
__device__ float d_Wh[NN * FF];
__device__ float d_WhT[FF * NN];
__device__ float d_Hout[NN * FF];
__device__ int   d_flags[NN];
__device__ int   d_list[NN];
__device__ int   d_count;
__device__ float d_pm[MAXUNITS * BM];
__device__ float d_pl[MAXUNITS * BM];
__device__ float d_pO[(size_t)MAXUNITS * BM * FF];   // 64 MB partial O

// ---------------- f32x2 helpers ----------------
__device__ __forceinline__ void ffma2(ull& d, ull a, ull b) {
    asm("fma.rn.f32x2 %0, %1, %2, %0;" : "+l"(d) : "l"(a), "l"(b));
}
__device__ __forceinline__ void mul2(ull& d, ull s) {
    asm("mul.rn.f32x2 %0, %0, %1;" : "+l"(d) : "l"(s));
}
__device__ __forceinline__ ull pack2(float lo, float hi) {
    ull r; asm("mov.b64 %0, {%1, %2};" : "=l"(r) : "f"(lo), "f"(hi)); return r;
}
__device__ __forceinline__ float2 unpack2(ull v) {
    float2 f; asm("mov.b64 {%0, %1}, %2;" : "=f"(f.x), "=f"(f.y) : "l"(v)); return f;
}

// ---------------- tiny setup kernels ----------------
__global__ void k_init() {
    int i = blockIdx.x * blockDim.x + threadIdx.x;
    if (i < NN) d_flags[i] = 0;
    if (i == 0) d_count = 0;
}
__global__ void k_mark(const int* __restrict__ x) {
    int i = blockIdx.x * blockDim.x + threadIdx.x;
    if (i < BB) d_flags[x[i]] = 1;
}
__global__ void k_compact() {
    int i = blockIdx.x * blockDim.x + threadIdx.x;
    if (i < NN && d_flags[i]) {
        int p = atomicAdd(&d_count, 1);
        d_list[p] = i;
    }
}

// ---------------- Wh = embedding @ W, plus Wh^T ----------------
__global__ __launch_bounds__(256) void k_whgemm(const float* __restrict__ emb,
                                                const float* __restrict__ W) {
    __shared__ float At[32][68];
    __shared__ float Bs[32][128];
    int tid = threadIdx.x, tx = tid & 31, ty = tid >> 5;
    int row0 = blockIdx.x * 64;
    float acc[8][4];
#pragma unroll
    for (int r = 0; r < 8; r++)
#pragma unroll
        for (int c = 0; c < 4; c++) acc[r][c] = 0.f;

    for (int k0 = 0; k0 < DD; k0 += 32) {
#pragma unroll
        for (int it = 0; it < 2; it++) {
            int id = it * 256 + tid;
            int r = id >> 3;
            int c4 = (id & 7) * 4;
            float4 v = *(const float4*)&emb[(row0 + r) * DD + k0 + c4];
            At[c4 + 0][r] = v.x; At[c4 + 1][r] = v.y;
            At[c4 + 2][r] = v.z; At[c4 + 3][r] = v.w;
        }
#pragma unroll
        for (int it = 0; it < 4; it++) {
            int id = it * 256 + tid;
            int r = id >> 5;
            int c4 = (id & 31) * 4;
            *(float4*)&Bs[r][c4] = *(const float4*)&W[(k0 + r) * FF + c4];
        }
        __syncthreads();
#pragma unroll
        for (int k = 0; k < 32; k++) {
            float4 a0 = *(const float4*)&At[k][8 * ty];
            float4 a1 = *(const float4*)&At[k][8 * ty + 4];
            float4 b  = *(const float4*)&Bs[k][4 * tx];
            float av[8] = {a0.x, a0.y, a0.z, a0.w, a1.x, a1.y, a1.z, a1.w};
            float bv[4] = {b.x, b.y, b.z, b.w};
#pragma unroll
            for (int r = 0; r < 8; r++)
#pragma unroll
                for (int c = 0; c < 4; c++) acc[r][c] += av[r] * bv[c];
        }
        __syncthreads();
    }
#pragma unroll
    for (int r = 0; r < 8; r++) {
        int row = row0 + 8 * ty + r;
        float4 v = make_float4(acc[r][0], acc[r][1], acc[r][2], acc[r][3]);
        *(float4*)&d_Wh[row * FF + 4 * tx] = v;
        d_WhT[(4 * tx + 0) * NN + row] = v.x;
        d_WhT[(4 * tx + 1) * NN + row] = v.y;
        d_WhT[(4 * tx + 2) * NN + row] = v.z;
        d_WhT[(4 * tx + 3) * NN + row] = v.w;
    }
}

// ---------------- fused masked attention: split-KV partials ----------------
// Smem = 3*32KB + 16KB = 114688 B exactly (14 x 8KB granules) -> 2 CTAs/SM.
struct AttnSmem {
    float whiT[FF][BM];   // Wh_I^T : [f][m]
    float whJT[FF][BN];   // Wh_J^T : [f][j]   (GEMM1 B)
    float whJ[BN][FF];    // Wh_J   : [j][f]   (GEMM2 B)
    float pt[BM][BN];     // P      : [m][j]
};

__global__ __launch_bounds__(256, 2) void k_attn(const int* __restrict__ adj) {
    extern __shared__ char smraw[];
    AttnSmem& sm = *(AttnSmem*)smraw;
    const int tid = threadIdx.x;
    const int i  = tid >> 4;   // 0..15 : rows 4i..4i+3
    const int jj = tid & 15;   // 0..15 : GEMM1 cols 4jj.., GEMM2 f 8jj..
    const int cnt = d_count;
    const int ntiles = (cnt + BM - 1) / BM;
    const int nunits = ntiles * JSPLIT;

    for (int u = blockIdx.x; u < nunits; u += gridDim.x) {
        const int tile  = u / JSPLIT;
        const int slice = u - tile * JSPLIT;
        const int jbase0 = slice * JCHUNK;

        __syncthreads();  // previous unit fully done before overwriting whiT

        // prologue: gather whiT[f][m] from d_WhT (conflict-free STS)
#pragma unroll
        for (int s = 0; s < 8; s++) {
            int id = s * 256 + tid;
            int f = id >> 4;
            int m4 = (id & 15) * 4;
            float v[4];
#pragma unroll
            for (int q = 0; q < 4; q++) {
                int ridx = tile * BM + m4 + q;
                int row = d_list[ridx < cnt ? ridx : cnt - 1];
                v[q] = d_WhT[(size_t)f * NN + row];
            }
            *(float4*)&sm.whiT[f][m4] = make_float4(v[0], v[1], v[2], v[3]);
        }
        size_t arow[4];
#pragma unroll
        for (int r = 0; r < 4; r++) {
            int ridx = tile * BM + 4 * i + r;
            arow[r] = (size_t)d_list[ridx < cnt ? ridx : cnt - 1] * NN;
        }

        float mrow[4], lrow[4];
        ull O2[4][4];
#pragma unroll
        for (int r = 0; r < 4; r++) {
            mrow[r] = -1e30f; lrow[r] = 0.f;
#pragma unroll
            for (int c = 0; c < 4; c++) O2[r][c] = 0ULL;
        }

        for (int it = 0; it < JITERS; it++) {
            int j0 = jbase0 + it * BN;
            // adjacency bits (issued early; consumed after GEMM1)
            int4 am[4];
#pragma unroll
            for (int r = 0; r < 4; r++)
                am[r] = *(const int4*)&adj[arow[r] + j0 + 4 * jj];

            // load J tile both layouts
#pragma unroll
            for (int s = 0; s < 8; s++) {
                int id = s * 256 + tid;
                int f = id >> 4;
                int c4 = (id & 15) * 4;
                *(float4*)&sm.whJT[f][c4] =
                    *(const float4*)&d_WhT[(size_t)f * NN + j0 + c4];
            }
#pragma unroll
            for (int s = 0; s < 8; s++) {
                int id = s * 256 + tid;
                int jr = id >> 5;
                int c4 = (id & 31) * 4;
                *(float4*)&sm.whJ[jr][c4] =
                    *(const float4*)&d_Wh[(size_t)(j0 + jr) * FF + c4];
            }
            __syncthreads();

            // GEMM1: S[4m][4j] = Wh_I . Wh_J^T  (f32x2, j packed in lanes)
            ull S2[4][2];
#pragma unroll
            for (int r = 0; r < 4; r++) { S2[r][0] = 0ULL; S2[r][1] = 0ULL; }
#pragma unroll 4
            for (int k = 0; k < FF; k++) {
                float4 a4 = *(const float4*)&sm.whiT[k][4 * i];
                ulonglong2 b2 = *(const ulonglong2*)&sm.whJT[k][4 * jj];
                float af[4] = {a4.x, a4.y, a4.z, a4.w};
#pragma unroll
                for (int r = 0; r < 4; r++) {
                    ull ad = pack2(af[r], af[r]);
                    ffma2(S2[r][0], ad, b2.x);
                    ffma2(S2[r][1], ad, b2.y);
                }
            }

            // masked online softmax (16-lane row groups)
#pragma unroll
            for (int r = 0; r < 4; r++) {
                float2 s01 = unpack2(S2[r][0]);
                float2 s23 = unpack2(S2[r][1]);
                float s0 = am[r].x ? s01.x : -1e30f;
                float s1 = am[r].y ? s01.y : -1e30f;
                float s2 = am[r].z ? s23.x : -1e30f;
                float s3 = am[r].w ? s23.y : -1e30f;
                float mx = fmaxf(fmaxf(s0, s1), fmaxf(s2, s3));
#pragma unroll
                for (int o = 8; o; o >>= 1)
                    mx = fmaxf(mx, __shfl_xor_sync(0xffffffffu, mx, o));
                if (mx > mrow[r]) {
                    float sc = __expf(mrow[r] - mx);
                    lrow[r] *= sc;
                    ull scp = pack2(sc, sc);
                    mul2(O2[r][0], scp); mul2(O2[r][1], scp);
                    mul2(O2[r][2], scp); mul2(O2[r][3], scp);
                    mrow[r] = mx;
                }
                float p0 = am[r].x ? __expf(s0 - mrow[r]) : 0.f;
                float p1 = am[r].y ? __expf(s1 - mrow[r]) : 0.f;
                float p2 = am[r].z ? __expf(s2 - mrow[r]) : 0.f;
                float p3 = am[r].w ? __expf(s3 - mrow[r]) : 0.f;
                lrow[r] += (p0 + p1) + (p2 + p3);
                *(float4*)&sm.pt[4 * i + r][4 * jj] = make_float4(p0, p1, p2, p3);
            }
            __syncthreads();

            // GEMM2: O[4m][8f] += P . Wh_J  (f32x2, f packed in lanes)
#pragma unroll 2
            for (int k = 0; k < BN; k++) {
                ulonglong2 ba = *(const ulonglong2*)&sm.whJ[k][8 * jj];
                ulonglong2 bb = *(const ulonglong2*)&sm.whJ[k][8 * jj + 4];
#pragma unroll
                for (int r = 0; r < 4; r++) {
                    float pv = sm.pt[4 * i + r][k];
                    ull pd = pack2(pv, pv);
                    ffma2(O2[r][0], pd, ba.x);
                    ffma2(O2[r][1], pd, ba.y);
                    ffma2(O2[r][2], pd, bb.x);
                    ffma2(O2[r][3], pd, bb.y);
                }
            }
            __syncthreads();
        }

        // epilogue: write partial (m, l, O) for this (tile, slice)
#pragma unroll
        for (int r = 0; r < 4; r++) {
            float l = lrow[r];
#pragma unroll
            for (int o = 8; o; o >>= 1) l += __shfl_xor_sync(0xffffffffu, l, o);
            size_t pbase = ((size_t)u * BM + 4 * i + r) * FF + 8 * jj;
            float2 o0 = unpack2(O2[r][0]);
            float2 o1 = unpack2(O2[r][1]);
            float2 o2 = unpack2(O2[r][2]);
            float2 o3 = unpack2(O2[r][3]);
            *(float4*)&d_pO[pbase]     = make_float4(o0.x, o0.y, o1.x, o1.y);
            *(float4*)&d_pO[pbase + 4] = make_float4(o2.x, o2.y, o3.x, o3.y);
            if (jj == 0) {
                d_pm[u * BM + 4 * i + r] = mrow[r];
                d_pl[u * BM + 4 * i + r] = l;
            }
        }
    }
}

// ---------------- combine partials + elu + L2 normalize ----------------
__global__ __launch_bounds__(128) void k_reduce() {
    int rid = blockIdx.x;
    int cnt = d_count;
    if (rid >= cnt) return;
    int tile = rid / BM, mloc = rid - tile * BM;
    int f = threadIdx.x;
    int base = tile * JSPLIT;

    float M = -1e30f;
#pragma unroll
    for (int s = 0; s < JSPLIT; s++)
        M = fmaxf(M, d_pm[(base + s) * BM + mloc]);
    float L = 0.f, acc = 0.f;
#pragma unroll
    for (int s = 0; s < JSPLIT; s++) {
        float w = __expf(d_pm[(base + s) * BM + mloc] - M);
        L += w * d_pl[(base + s) * BM + mloc];
        acc += w * d_pO[((size_t)(base + s) * BM + mloc) * FF + f];
    }
    float v = acc / L;
    v = (v > 0.f) ? v : expm1f(v);

    __shared__ float red[4];
    float ssq = v * v;
#pragma unroll
    for (int o = 16; o; o >>= 1) ssq += __shfl_xor_sync(0xffffffffu, ssq, o);
    int lane = f & 31, w = f >> 5;
    if (lane == 0) red[w] = ssq;
    __syncthreads();
    ssq = red[0] + red[1] + red[2] + red[3];
    float inn = 1.f / fmaxf(sqrtf(ssq), 1e-12f);
    d_Hout[(size_t)d_list[rid] * FF + f] = v * inn;
}

// ---------------- output gather ----------------
__global__ void k_gather(const int* __restrict__ x, float* __restrict__ out) {
    int id = blockIdx.x * blockDim.x + threadIdx.x;
    if (id < BB * 32) {
        int b = id >> 5;
        int c4 = (id & 31) * 4;
        *(float4*)&out[b * FF + c4] = *(const float4*)&d_Hout[(size_t)x[b] * FF + c4];
    }
}

extern "C" void kernel_launch(void* const* d_in, const int* in_sizes, int n_in,
                              void* d_out, int out_size) {
    const int*   x   = (const int*)d_in[0];
    const int*   adj = (const int*)d_in[1];
    const float* emb = (const float*)d_in[2];
    const float* W   = (const float*)d_in[3];
    float* out = (float*)d_out;

    cudaFuncSetAttribute(k_attn, cudaFuncAttributeMaxDynamicSharedMemorySize,
                         (int)sizeof(AttnSmem));

    k_init<<<(NN + 255) / 256, 256>>>();
    k_mark<<<(BB + 255) / 256, 256>>>(x);
    k_compact<<<(NN + 255) / 256, 256>>>();
    k_whgemm<<<NN / 64, 256>>>(emb, W);
    k_attn<<<ATTN_GRID, 256, sizeof(AttnSmem)>>>(adj);
    k_reduce<<<NN, 128>>>();
    k_gather<<<(BB * 32 + 255) / 256, 256>>>(x, out);
}

// round 6
// speedup vs baseline: 3.3342x; 2.0211x over previous
#include <cuda_runtime.h>
#include <cuda_bf16.h>
#include <math.h>
#include <stdint.h>

#define NN 8192
#define DD 256
#define FF 128
#define BB 4096
#define JSPLIT 16
#define MAXT 32
#define MAXU (MAXT * JSPLIT)   // 512

#define SA_HI 0
#define SA_LO 32768
#define SJ_HI 65536
#define SJ_LO 98304
#define SM_TOTAL 131072

// ---------------- device scratch ----------------
__device__ float d_Wh[NN * FF];
__device__ float d_Hout[NN * FF];
__device__ int d_flags[NN], d_list[NN], d_count;
__device__ uint32_t d_adjb[4096 * 256];          // bit-packed adj per compacted row
__device__ uint4 d_iJh[NN * 16], d_iJl[NN * 16]; // Wh bf16 hi/lo [j][f]
__device__ uint4 d_iAh[MAXT * 2048], d_iAl[MAXT * 2048]; // gathered I tiles
__device__ float d_pm[MAXU * 128], d_pl[MAXU * 128];
__device__ float d_pO[(size_t)MAXU * 128 * FF];  // 33.5 MB partials

// ---------------- helpers ----------------
__device__ __forceinline__ uint32_t smem_u32(const void* p) {
    uint32_t a;
    asm("{ .reg .u64 t; cvta.to.shared.u64 t, %1; cvt.u32.u64 %0, t; }" : "=r"(a) : "l"(p));
    return a;
}
__device__ __forceinline__ float bf16r(float x) {
    return __bfloat162float(__float2bfloat16(x));
}
__device__ __forceinline__ uint32_t packbf(float lo, float hi) {
    uint32_t r;
    asm("cvt.rn.bf16x2.f32 %0, %1, %2;" : "=r"(r) : "f"(hi), "f"(lo));
    return r;
}
__device__ __forceinline__ void split8(const float* v, uint4& h, uint4& l) {
    uint32_t hw[4], lw[4];
#pragma unroll
    for (int p = 0; p < 4; p++) {
        float a = v[2 * p], b = v[2 * p + 1];
        float ah = bf16r(a), bh = bf16r(b);
        hw[p] = packbf(ah, bh);
        lw[p] = packbf(a - ah, b - bh);
    }
    h = make_uint4(hw[0], hw[1], hw[2], hw[3]);
    l = make_uint4(lw[0], lw[1], lw[2], lw[3]);
}
__device__ __forceinline__ void ldsm4(uint32_t* r, uint32_t addr) {
    asm volatile("ldmatrix.sync.aligned.m8n8.x4.shared.b16 {%0,%1,%2,%3}, [%4];"
                 : "=r"(r[0]), "=r"(r[1]), "=r"(r[2]), "=r"(r[3]) : "r"(addr));
}
__device__ __forceinline__ void ldsm2(uint32_t* r, uint32_t addr) {
    asm volatile("ldmatrix.sync.aligned.m8n8.x2.shared.b16 {%0,%1}, [%2];"
                 : "=r"(r[0]), "=r"(r[1]) : "r"(addr));
}
__device__ __forceinline__ void ldsm2t(uint32_t* r, uint32_t addr) {
    asm volatile("ldmatrix.sync.aligned.m8n8.x2.trans.shared.b16 {%0,%1}, [%2];"
                 : "=r"(r[0]), "=r"(r[1]) : "r"(addr));
}
__device__ __forceinline__ void mma16816(float* d, const uint32_t* a, const uint32_t* b) {
    asm volatile("mma.sync.aligned.m16n8k16.row.col.f32.bf16.bf16.f32 "
                 "{%0,%1,%2,%3}, {%4,%5,%6,%7}, {%8,%9}, {%0,%1,%2,%3};"
                 : "+f"(d[0]), "+f"(d[1]), "+f"(d[2]), "+f"(d[3])
                 : "r"(a[0]), "r"(a[1]), "r"(a[2]), "r"(a[3]), "r"(b[0]), "r"(b[1]));
}

// ---------------- setup kernels ----------------
__global__ void k_init() {
    int i = blockIdx.x * blockDim.x + threadIdx.x;
    if (i < NN) d_flags[i] = 0;
    if (i == 0) d_count = 0;
}
__global__ void k_mark(const int* __restrict__ x) {
    int i = blockIdx.x * blockDim.x + threadIdx.x;
    if (i < BB) d_flags[x[i]] = 1;
}
__global__ void k_compact() {
    int i = blockIdx.x * blockDim.x + threadIdx.x;
    if (i < NN && d_flags[i]) {
        int p = atomicAdd(&d_count, 1);
        d_list[p] = i;
    }
}

// ---------------- Wh = embedding @ W ----------------
__global__ __launch_bounds__(256) void k_whgemm(const float* __restrict__ emb,
                                                const float* __restrict__ W) {
    __shared__ float At[32][68];
    __shared__ float Bs[32][128];
    int tid = threadIdx.x, tx = tid & 31, ty = tid >> 5;
    int row0 = blockIdx.x * 64;
    float acc[8][4];
#pragma unroll
    for (int r = 0; r < 8; r++)
#pragma unroll
        for (int c = 0; c < 4; c++) acc[r][c] = 0.f;
    for (int k0 = 0; k0 < DD; k0 += 32) {
#pragma unroll
        for (int it = 0; it < 2; it++) {
            int id = it * 256 + tid;
            int r = id >> 3, c4 = (id & 7) * 4;
            float4 v = *(const float4*)&emb[(row0 + r) * DD + k0 + c4];
            At[c4 + 0][r] = v.x; At[c4 + 1][r] = v.y;
            At[c4 + 2][r] = v.z; At[c4 + 3][r] = v.w;
        }
#pragma unroll
        for (int it = 0; it < 4; it++) {
            int id = it * 256 + tid;
            int r = id >> 5, c4 = (id & 31) * 4;
            *(float4*)&Bs[r][c4] = *(const float4*)&W[(k0 + r) * FF + c4];
        }
        __syncthreads();
#pragma unroll
        for (int k = 0; k < 32; k++) {
            float4 a0 = *(const float4*)&At[k][8 * ty];
            float4 a1 = *(const float4*)&At[k][8 * ty + 4];
            float4 b  = *(const float4*)&Bs[k][4 * tx];
            float av[8] = {a0.x, a0.y, a0.z, a0.w, a1.x, a1.y, a1.z, a1.w};
            float bv[4] = {b.x, b.y, b.z, b.w};
#pragma unroll
            for (int r = 0; r < 8; r++)
#pragma unroll
                for (int c = 0; c < 4; c++) acc[r][c] += av[r] * bv[c];
        }
        __syncthreads();
    }
#pragma unroll
    for (int r = 0; r < 8; r++)
        *(float4*)&d_Wh[(row0 + 8 * ty + r) * FF + 4 * tx] =
            make_float4(acc[r][0], acc[r][1], acc[r][2], acc[r][3]);
}

// ---------------- image builders ----------------
__global__ void k_imgJ() {
    int idx = blockIdx.x * 256 + threadIdx.x;      // NN*16
    int row = idx >> 4, c = idx & 15;
    float v[8];
    *(float4*)&v[0] = *(const float4*)&d_Wh[(size_t)row * FF + c * 8];
    *(float4*)&v[4] = *(const float4*)&d_Wh[(size_t)row * FF + c * 8 + 4];
    uint4 h, l; split8(v, h, l);
    d_iJh[idx] = h; d_iJl[idx] = l;
}
__global__ void k_imgA() {
    int idx = blockIdx.x * 256 + threadIdx.x;      // MAXT*2048
    int tile = idx >> 11, gc = idx & 2047;
    int cnt = d_count;
    if (tile >= (cnt + 127) >> 7) return;
    int row = gc >> 4, c = gc & 15;
    int ridx = tile * 128 + row; if (ridx >= cnt) ridx = cnt - 1;
    const float* src = &d_Wh[(size_t)d_list[ridx] * FF + c * 8];
    float v[8];
    *(float4*)&v[0] = *(const float4*)&src[0];
    *(float4*)&v[4] = *(const float4*)&src[4];
    uint4 h, l; split8(v, h, l);
    d_iAh[idx] = h; d_iAl[idx] = l;
}
__global__ void k_adjpack(const int* __restrict__ adj) {
    int b = blockIdx.x;
    int row = b >> 5, seg = b & 31;
    if (row >= d_count) return;
    size_t grow = (size_t)d_list[row] * NN;
    int j = seg * 256 + threadIdx.x;
    uint32_t bal = __ballot_sync(0xffffffffu, adj[grow + j] != 0);
    if ((threadIdx.x & 31) == 0) d_adjb[row * 256 + (j >> 5)] = bal;
}

// ---------------- mma.sync fused attention ----------------
__global__ __launch_bounds__(256, 1) void k_attn() {
    extern __shared__ char smc[];
    uint32_t smb = smem_u32(smc);
    const int tid = threadIdx.x, wid = tid >> 5, lane = tid & 31;
    const int g = lane >> 2, t = lane & 3;
    const int m0 = wid * 16;
    const int cnt = d_count;
    const int ntiles = (cnt + 127) >> 7;
    const int nunits = ntiles * JSPLIT;

    const int arow = m0 + (lane & 15);
    const uint32_t acolx = (lane & 16) ? 16u : 0u;
    const uint32_t abase = smb + (uint32_t)arow * 256;
    const uint32_t arot = (uint32_t)(arow & 7) * 16;

    for (int u = blockIdx.x; u < nunits; u += gridDim.x) {
        const int tile = u >> 4, sl = u & 15;
        __syncthreads();   // protect Wh_I from warps still in previous unit
        {
            const uint4* gh = &d_iAh[tile * 2048];
            const uint4* gl = &d_iAl[tile * 2048];
#pragma unroll
            for (int s = 0; s < 8; s++) {
                int idx = s * 256 + tid;
                int row = idx >> 4, c = idx & 15;
                uint32_t off = (uint32_t)row * 256 + (((uint32_t)c * 16) ^ ((row & 7) * 16));
                *(uint4*)(smc + SA_HI + off) = gh[idx];
                *(uint4*)(smc + SA_LO + off) = gl[idx];
            }
        }
        int rA = tile * 128 + m0 + g;
        int rB = rA + 8;
        int rAc = rA < cnt ? rA : cnt - 1;
        int rBc = rB < cnt ? rB : cnt - 1;

        float O[16][4];
#pragma unroll
        for (int ft = 0; ft < 16; ft++)
            O[ft][0] = O[ft][1] = O[ft][2] = O[ft][3] = 0.f;
        float mr0 = -1e30f, mr1 = -1e30f, l0 = 0.f, l1 = 0.f;

#pragma unroll 1
        for (int jt = 0; jt < 4; jt++) {
            const int j0 = sl * 512 + jt * 128;
            __syncthreads();   // previous GEMM2 done reading Wh_J
            {
                const uint4* gh = &d_iJh[j0 * 16];
                const uint4* gl = &d_iJl[j0 * 16];
#pragma unroll
                for (int s = 0; s < 8; s++) {
                    int idx = s * 256 + tid;
                    int row = idx >> 4, c = idx & 15;
                    uint32_t off = (uint32_t)row * 256 + (((uint32_t)c * 16) ^ ((row & 7) * 16));
                    *(uint4*)(smc + SJ_HI + off) = gh[idx];
                    *(uint4*)(smc + SJ_LO + off) = gl[idx];
                }
            }
            __syncthreads();
            uint4 awA = *(const uint4*)&d_adjb[rAc * 256 + (j0 >> 5)];
            uint4 awB = *(const uint4*)&d_adjb[rBc * 256 + (j0 >> 5)];
            const uint32_t* wa = &awA.x;
            const uint32_t* wb = &awB.x;

#pragma unroll
            for (int h = 0; h < 2; h++) {
                // ---- GEMM1: S = Wh_I . Wh_J^T (3-pass bf16) ----
                float S[8][4];
#pragma unroll
                for (int nt = 0; nt < 8; nt++)
                    S[nt][0] = S[nt][1] = S[nt][2] = S[nt][3] = 0.f;
#pragma unroll 2
                for (int q = 0; q < 8; q++) {
                    uint32_t ah[4], al[4];
                    uint32_t aoff = ((uint32_t)(q * 32) + acolx) ^ arot;
                    ldsm4(ah, abase + SA_HI + aoff);
                    ldsm4(al, abase + SA_LO + aoff);
#pragma unroll
                    for (int nt = 0; nt < 8; nt++) {
                        int brow = h * 64 + nt * 8 + (lane & 7);
                        uint32_t boff = (uint32_t)brow * 256 +
                            (((uint32_t)(q * 32) + ((lane & 8) ? 16u : 0u)) ^ ((brow & 7) * 16));
                        uint32_t bh[2], bl[2];
                        ldsm2(bh, smb + SJ_HI + boff);
                        ldsm2(bl, smb + SJ_LO + boff);
                        mma16816(S[nt], ah, bh);
                        mma16816(S[nt], ah, bl);
                        mma16816(S[nt], al, bh);
                    }
                }
                // ---- masked online softmax (quad owns rows rA, rB) ----
                float tmA = -1e30f, tmB = -1e30f;
#pragma unroll
                for (int nt = 0; nt < 8; nt++) {
                    int bp = (h * 64 + nt * 8 + 2 * t) & 31;
                    uint32_t mA = wa[h * 2 + (nt >> 2)] >> bp;
                    uint32_t mB = wb[h * 2 + (nt >> 2)] >> bp;
                    if (mA & 1) tmA = fmaxf(tmA, S[nt][0]);
                    if (mA & 2) tmA = fmaxf(tmA, S[nt][1]);
                    if (mB & 1) tmB = fmaxf(tmB, S[nt][2]);
                    if (mB & 2) tmB = fmaxf(tmB, S[nt][3]);
                }
                tmA = fmaxf(tmA, __shfl_xor_sync(0xffffffffu, tmA, 1));
                tmA = fmaxf(tmA, __shfl_xor_sync(0xffffffffu, tmA, 2));
                tmB = fmaxf(tmB, __shfl_xor_sync(0xffffffffu, tmB, 1));
                tmB = fmaxf(tmB, __shfl_xor_sync(0xffffffffu, tmB, 2));
                float nmA = fmaxf(mr0, tmA), nmB = fmaxf(mr1, tmB);
                float scA = __expf(mr0 - nmA), scB = __expf(mr1 - nmB);
                mr0 = nmA; mr1 = nmB;
                l0 *= scA; l1 *= scB;
#pragma unroll
                for (int ft = 0; ft < 16; ft++) {
                    O[ft][0] *= scA; O[ft][1] *= scA;
                    O[ft][2] *= scB; O[ft][3] *= scB;
                }
                // ---- P = exp(S-m), packed directly as GEMM2 A-frags ----
                uint32_t phi[16], plo[16];
#pragma unroll
                for (int nt = 0; nt < 8; nt++) {
                    int bp = (h * 64 + nt * 8 + 2 * t) & 31;
                    uint32_t mA = wa[h * 2 + (nt >> 2)] >> bp;
                    uint32_t mB = wb[h * 2 + (nt >> 2)] >> bp;
                    float p0 = (mA & 1) ? __expf(S[nt][0] - mr0) : 0.f;
                    float p1 = (mA & 2) ? __expf(S[nt][1] - mr0) : 0.f;
                    float p2 = (mB & 1) ? __expf(S[nt][2] - mr1) : 0.f;
                    float p3 = (mB & 2) ? __expf(S[nt][3] - mr1) : 0.f;
                    l0 += p0 + p1; l1 += p2 + p3;
                    float h0 = bf16r(p0), h1 = bf16r(p1), h2 = bf16r(p2), h3 = bf16r(p3);
                    int base = (nt >> 1) * 4 + (nt & 1) * 2;
                    phi[base + 0] = packbf(h0, h1);
                    phi[base + 1] = packbf(h2, h3);
                    plo[base + 0] = packbf(p0 - h0, p1 - h1);
                    plo[base + 1] = packbf(p2 - h2, p3 - h3);
                }
                // ---- GEMM2: O += P . Wh_J (3-pass; B via ldmatrix.trans) ----
#pragma unroll
                for (int q2 = 0; q2 < 4; q2++) {
                    int brow = h * 64 + q2 * 16 + (lane & 15);
                    uint32_t brb = (uint32_t)brow * 256;
                    uint32_t rot = (uint32_t)(brow & 7) * 16;
#pragma unroll
                    for (int ft = 0; ft < 16; ft++) {
                        uint32_t boff = brb + (((uint32_t)ft * 16) ^ rot);
                        uint32_t bh[2], bl[2];
                        ldsm2t(bh, smb + SJ_HI + boff);
                        ldsm2t(bl, smb + SJ_LO + boff);
                        mma16816(O[ft], &phi[q2 * 4], bh);
                        mma16816(O[ft], &phi[q2 * 4], bl);
                        mma16816(O[ft], &plo[q2 * 4], bh);
                    }
                }
            }
        }
        // ---- epilogue: quad-reduce l, store partials ----
        l0 += __shfl_xor_sync(0xffffffffu, l0, 1);
        l0 += __shfl_xor_sync(0xffffffffu, l0, 2);
        l1 += __shfl_xor_sync(0xffffffffu, l1, 1);
        l1 += __shfl_xor_sync(0xffffffffu, l1, 2);
        int lrowA = m0 + g, lrowB = m0 + 8 + g;
        if (t == 0) {
            d_pm[u * 128 + lrowA] = mr0; d_pl[u * 128 + lrowA] = l0;
            d_pm[u * 128 + lrowB] = mr1; d_pl[u * 128 + lrowB] = l1;
        }
        size_t baseA = ((size_t)u * 128 + lrowA) * FF + 2 * t;
        size_t baseB = ((size_t)u * 128 + lrowB) * FF + 2 * t;
#pragma unroll
        for (int ft = 0; ft < 16; ft++) {
            *(float2*)&d_pO[baseA + ft * 8] = make_float2(O[ft][0], O[ft][1]);
            *(float2*)&d_pO[baseB + ft * 8] = make_float2(O[ft][2], O[ft][3]);
        }
    }
}

// ---------------- combine partials + elu + L2 normalize ----------------
__global__ __launch_bounds__(128) void k_reduce() {
    int rid = blockIdx.x, cnt = d_count;
    if (rid >= cnt) return;
    int tile = rid >> 7, m = rid & 127;
    int f = threadIdx.x;
    int base = tile * JSPLIT;
    float M = -1e30f;
#pragma unroll
    for (int s = 0; s < JSPLIT; s++) M = fmaxf(M, d_pm[(base + s) * 128 + m]);
    float L = 0.f, acc = 0.f;
#pragma unroll 4
    for (int s = 0; s < JSPLIT; s++) {
        float w = __expf(d_pm[(base + s) * 128 + m] - M);
        L += w * d_pl[(base + s) * 128 + m];
        acc += w * d_pO[((size_t)(base + s) * 128 + m) * FF + f];
    }
    float v = acc / L;
    v = (v > 0.f) ? v : expm1f(v);
    __shared__ float red[4];
    float ssq = v * v;
#pragma unroll
    for (int o = 16; o; o >>= 1) ssq += __shfl_xor_sync(0xffffffffu, ssq, o);
    if ((f & 31) == 0) red[f >> 5] = ssq;
    __syncthreads();
    ssq = red[0] + red[1] + red[2] + red[3];
    float inn = 1.f / fmaxf(sqrtf(ssq), 1e-12f);
    d_Hout[(size_t)d_list[rid] * FF + f] = v * inn;
}

__global__ void k_gather(const int* __restrict__ x, float* __restrict__ out) {
    int id = blockIdx.x * blockDim.x + threadIdx.x;
    if (id < BB * 32) {
        int b = id >> 5;
        int c4 = (id & 31) * 4;
        *(float4*)&out[b * FF + c4] = *(const float4*)&d_Hout[(size_t)x[b] * FF + c4];
    }
}

extern "C" void kernel_launch(void* const* d_in, const int* in_sizes, int n_in,
                              void* d_out, int out_size) {
    const int*   x   = (const int*)d_in[0];
    const int*   adj = (const int*)d_in[1];
    const float* emb = (const float*)d_in[2];
    const float* W   = (const float*)d_in[3];
    float* out = (float*)d_out;

    cudaFuncSetAttribute(k_attn, cudaFuncAttributeMaxDynamicSharedMemorySize, SM_TOTAL);

    k_init<<<32, 256>>>();
    k_mark<<<16, 256>>>(x);
    k_compact<<<32, 256>>>();
    k_whgemm<<<128, 256>>>(emb, W);
    k_adjpack<<<4096 * 32, 256>>>(adj);
    k_imgJ<<<512, 256>>>();
    k_imgA<<<256, 256>>>();
    k_attn<<<148, 256, SM_TOTAL>>>();
    k_reduce<<<4096, 128>>>();
    k_gather<<<512, 256>>>(x, out);
}

// round 7
// speedup vs baseline: 4.6239x; 1.3868x over previous
#include <cuda_runtime.h>
#include <cuda_bf16.h>
#include <math.h>
#include <stdint.h>

#define NN 8192
#define DD 256
#define FF 128
#define BB 4096
#define JSPLIT 16
#define MAXT 32
#define MAXU (MAXT * JSPLIT)   // 512

#define SA_HI 0
#define SA_LO 32768
#define SJB(b) (65536 + (b) * 65536)
#define SM_TOTAL 196608

// ---------------- device scratch ----------------
__device__ float d_Wh[NN * FF];
__device__ float d_Hout[NN * FF];
__device__ int d_flags[NN], d_list[NN], d_count;
__device__ uint32_t d_adjb[4096 * 256];
__device__ uint4 d_iJh[NN * 16], d_iJl[NN * 16];
__device__ uint4 d_iAh[MAXT * 2048], d_iAl[MAXT * 2048];
__device__ float d_pm[MAXU * 128], d_pl[MAXU * 128];
__device__ float d_pO[(size_t)MAXU * 128 * FF];

// ---------------- helpers ----------------
__device__ __forceinline__ uint32_t smem_u32(const void* p) {
    uint32_t a;
    asm("{ .reg .u64 t; cvta.to.shared.u64 t, %1; cvt.u32.u64 %0, t; }" : "=r"(a) : "l"(p));
    return a;
}
__device__ __forceinline__ float bf16r(float x) {
    return __bfloat162float(__float2bfloat16(x));
}
__device__ __forceinline__ uint32_t packbf(float lo, float hi) {
    uint32_t r;
    asm("cvt.rn.bf16x2.f32 %0, %1, %2;" : "=r"(r) : "f"(hi), "f"(lo));
    return r;
}
__device__ __forceinline__ void split8(const float* v, uint4& h, uint4& l) {
    uint32_t hw[4], lw[4];
#pragma unroll
    for (int p = 0; p < 4; p++) {
        float a = v[2 * p], b = v[2 * p + 1];
        float ah = bf16r(a), bh = bf16r(b);
        hw[p] = packbf(ah, bh);
        lw[p] = packbf(a - ah, b - bh);
    }
    h = make_uint4(hw[0], hw[1], hw[2], hw[3]);
    l = make_uint4(lw[0], lw[1], lw[2], lw[3]);
}
__device__ __forceinline__ void ldsm4(uint32_t* r, uint32_t addr) {
    asm volatile("ldmatrix.sync.aligned.m8n8.x4.shared.b16 {%0,%1,%2,%3}, [%4];"
                 : "=r"(r[0]), "=r"(r[1]), "=r"(r[2]), "=r"(r[3]) : "r"(addr));
}
__device__ __forceinline__ void ldsm4t(uint32_t* r, uint32_t addr) {
    asm volatile("ldmatrix.sync.aligned.m8n8.x4.trans.shared.b16 {%0,%1,%2,%3}, [%4];"
                 : "=r"(r[0]), "=r"(r[1]), "=r"(r[2]), "=r"(r[3]) : "r"(addr));
}
__device__ __forceinline__ void mma16816(float* d, const uint32_t* a, const uint32_t* b) {
    asm volatile("mma.sync.aligned.m16n8k16.row.col.f32.bf16.bf16.f32 "
                 "{%0,%1,%2,%3}, {%4,%5,%6,%7}, {%8,%9}, {%0,%1,%2,%3};"
                 : "+f"(d[0]), "+f"(d[1]), "+f"(d[2]), "+f"(d[3])
                 : "r"(a[0]), "r"(a[1]), "r"(a[2]), "r"(a[3]), "r"(b[0]), "r"(b[1]));
}
#define CPA(dst, src) \
    asm volatile("cp.async.cg.shared.global [%0], [%1], 16;" :: "r"(dst), "l"(src))
#define CPC() asm volatile("cp.async.commit_group;" ::: "memory")
#define CPW(n) asm volatile("cp.async.wait_group %0;" :: "n"(n) : "memory")

// ---------------- setup kernels ----------------
__global__ void k_init() {
    int i = blockIdx.x * blockDim.x + threadIdx.x;
    if (i < NN) d_flags[i] = 0;
    if (i == 0) d_count = 0;
}
__global__ void k_mark(const int* __restrict__ x) {
    int i = blockIdx.x * blockDim.x + threadIdx.x;
    if (i < BB) d_flags[x[i]] = 1;
}
__global__ void k_compact() {
    int i = blockIdx.x * blockDim.x + threadIdx.x;
    if (i < NN && d_flags[i]) {
        int p = atomicAdd(&d_count, 1);
        d_list[p] = i;
    }
}

// ---------------- Wh = embedding @ W ----------------
__global__ __launch_bounds__(256) void k_whgemm(const float* __restrict__ emb,
                                                const float* __restrict__ W) {
    __shared__ float At[32][68];
    __shared__ float Bs[32][128];
    int tid = threadIdx.x, tx = tid & 31, ty = tid >> 5;
    int row0 = blockIdx.x * 64;
    float acc[8][4];
#pragma unroll
    for (int r = 0; r < 8; r++)
#pragma unroll
        for (int c = 0; c < 4; c++) acc[r][c] = 0.f;
    for (int k0 = 0; k0 < DD; k0 += 32) {
#pragma unroll
        for (int it = 0; it < 2; it++) {
            int id = it * 256 + tid;
            int r = id >> 3, c4 = (id & 7) * 4;
            float4 v = *(const float4*)&emb[(row0 + r) * DD + k0 + c4];
            At[c4 + 0][r] = v.x; At[c4 + 1][r] = v.y;
            At[c4 + 2][r] = v.z; At[c4 + 3][r] = v.w;
        }
#pragma unroll
        for (int it = 0; it < 4; it++) {
            int id = it * 256 + tid;
            int r = id >> 5, c4 = (id & 31) * 4;
            *(float4*)&Bs[r][c4] = *(const float4*)&W[(k0 + r) * FF + c4];
        }
        __syncthreads();
#pragma unroll
        for (int k = 0; k < 32; k++) {
            float4 a0 = *(const float4*)&At[k][8 * ty];
            float4 a1 = *(const float4*)&At[k][8 * ty + 4];
            float4 b  = *(const float4*)&Bs[k][4 * tx];
            float av[8] = {a0.x, a0.y, a0.z, a0.w, a1.x, a1.y, a1.z, a1.w};
            float bv[4] = {b.x, b.y, b.z, b.w};
#pragma unroll
            for (int r = 0; r < 8; r++)
#pragma unroll
                for (int c = 0; c < 4; c++) acc[r][c] += av[r] * bv[c];
        }
        __syncthreads();
    }
#pragma unroll
    for (int r = 0; r < 8; r++)
        *(float4*)&d_Wh[(row0 + 8 * ty + r) * FF + 4 * tx] =
            make_float4(acc[r][0], acc[r][1], acc[r][2], acc[r][3]);
}

// ---------------- image builders ----------------
__global__ void k_imgJ() {
    int idx = blockIdx.x * 256 + threadIdx.x;
    int row = idx >> 4, c = idx & 15;
    float v[8];
    *(float4*)&v[0] = *(const float4*)&d_Wh[(size_t)row * FF + c * 8];
    *(float4*)&v[4] = *(const float4*)&d_Wh[(size_t)row * FF + c * 8 + 4];
    uint4 h, l; split8(v, h, l);
    d_iJh[idx] = h; d_iJl[idx] = l;
}
__global__ void k_imgA() {
    int idx = blockIdx.x * 256 + threadIdx.x;
    int tile = idx >> 11, gc = idx & 2047;
    int cnt = d_count;
    if (tile >= (cnt + 127) >> 7) return;
    int row = gc >> 4, c = gc & 15;
    int ridx = tile * 128 + row; if (ridx >= cnt) ridx = cnt - 1;
    const float* src = &d_Wh[(size_t)d_list[ridx] * FF + c * 8];
    float v[8];
    *(float4*)&v[0] = *(const float4*)&src[0];
    *(float4*)&v[4] = *(const float4*)&src[4];
    uint4 h, l; split8(v, h, l);
    d_iAh[idx] = h; d_iAl[idx] = l;
}
__global__ __launch_bounds__(256) void k_adjpack(const int* __restrict__ adj) {
    int row = blockIdx.x;
    if (row >= d_count) return;
    size_t grow = (size_t)d_list[row] * NN;
    int tid = threadIdx.x, lane = tid & 31;
#pragma unroll 4
    for (int it = 0; it < 32; it++) {
        int j = it * 256 + tid;
        uint32_t bal = __ballot_sync(0xffffffffu, adj[grow + j] != 0);
        if (lane == 0) d_adjb[row * 256 + (j >> 5)] = bal;
    }
}

// ---------------- mma.sync fused attention (pipelined) ----------------
__global__ __launch_bounds__(256, 1) void k_attn() {
    extern __shared__ char smc[];
    uint32_t smb = smem_u32(smc);
    const int tid = threadIdx.x, wid = tid >> 5, lane = tid & 31;
    const int g = lane >> 2, t = lane & 3;
    const int m0 = wid * 16;
    const int cnt = d_count;
    const int ntiles = (cnt + 127) >> 7;
    const int nunits = ntiles * JSPLIT;

    // A fragment addressing (ldsm4: rows via lane&15, col-halves via lane&16)
    const int arow = m0 + (lane & 15);
    const uint32_t acolx = (lane & 16) ? 16u : 0u;
    const uint32_t abase = smb + (uint32_t)arow * 256;
    const uint32_t arot = (uint32_t)(arow & 7) * 16;

    // cp.async store offsets for this thread (row/col of the 2048-uint4 image)
    // idx = s*256 + tid; row = idx>>4, c = idx&15
    uint32_t stoff[8];
#pragma unroll
    for (int s = 0; s < 8; s++) {
        int idx = s * 256 + tid;
        int row = idx >> 4, c = idx & 15;
        stoff[s] = (uint32_t)row * 256 + (((uint32_t)c * 16) ^ ((row & 7) * 16));
    }

    for (int u = blockIdx.x; u < nunits; u += gridDim.x) {
        const int tile = u >> 4, sl = u & 15;
        __syncthreads();   // prior unit fully done with all smem

        // issue A + J0 loads (group 0)
        {
            const uint4* gah = &d_iAh[tile * 2048];
            const uint4* gal = &d_iAl[tile * 2048];
            const uint4* gjh = &d_iJh[(sl * 512) * 16];
            const uint4* gjl = &d_iJl[(sl * 512) * 16];
#pragma unroll
            for (int s = 0; s < 8; s++) {
                int idx = s * 256 + tid;
                CPA(smb + SA_HI + stoff[s], gah + idx);
                CPA(smb + SA_LO + stoff[s], gal + idx);
                CPA(smb + SJB(0) + stoff[s], gjh + idx);
                CPA(smb + SJB(0) + 32768 + stoff[s], gjl + idx);
            }
            CPC();
        }

        int rA = tile * 128 + m0 + g;
        int rB = rA + 8;
        int rAc = rA < cnt ? rA : cnt - 1;
        int rBc = rB < cnt ? rB : cnt - 1;

        float O[16][4];
#pragma unroll
        for (int ft = 0; ft < 16; ft++)
            O[ft][0] = O[ft][1] = O[ft][2] = O[ft][3] = 0.f;
        float mr0 = -1e30f, mr1 = -1e30f, l0 = 0.f, l1 = 0.f;

#pragma unroll 1
        for (int jt = 0; jt < 4; jt++) {
            const int j0 = sl * 512 + jt * 128;
            const uint32_t sjc = smb + SJB(jt & 1);

            if (jt > 0) __syncthreads();    // prev compute done before reusing buffer
            if (jt < 3) {                   // prefetch next jt
                const uint4* gjh = &d_iJh[(j0 + 128) * 16];
                const uint4* gjl = &d_iJl[(j0 + 128) * 16];
                uint32_t sjn = smb + SJB((jt + 1) & 1);
#pragma unroll
                for (int s = 0; s < 8; s++) {
                    int idx = s * 256 + tid;
                    CPA(sjn + stoff[s], gjh + idx);
                    CPA(sjn + 32768 + stoff[s], gjl + idx);
                }
                CPC();
                CPW(1);
            } else {
                CPW(0);
            }
            __syncthreads();                // current buffer visible to all

            uint4 awA = *(const uint4*)&d_adjb[rAc * 256 + (j0 >> 5)];
            uint4 awB = *(const uint4*)&d_adjb[rBc * 256 + (j0 >> 5)];
            const uint32_t* wa = &awA.x;
            const uint32_t* wb = &awB.x;

#pragma unroll
            for (int h = 0; h < 2; h++) {
                // ---- GEMM1: S(hi.hi) + C(cross) for independent mma chains ----
                float S[8][4], C[8][4];
#pragma unroll
                for (int nt = 0; nt < 8; nt++)
#pragma unroll
                    for (int c = 0; c < 4; c++) { S[nt][c] = 0.f; C[nt][c] = 0.f; }
#pragma unroll 2
                for (int q = 0; q < 8; q++) {
                    uint32_t ah[4], al[4];
                    uint32_t aoff = ((uint32_t)(q * 32) + acolx) ^ arot;
                    ldsm4(ah, abase + SA_HI + aoff);
                    ldsm4(al, abase + SA_LO + aoff);
#pragma unroll
                    for (int ntp = 0; ntp < 4; ntp++) {
                        int brow = h * 64 + ntp * 16 + ((lane >> 4) & 1) * 8 + (lane & 7);
                        uint32_t boff = (uint32_t)brow * 256 +
                            (((uint32_t)(q * 32) + ((lane & 8) ? 16u : 0u)) ^ ((brow & 7) * 16));
                        uint32_t bh[4], bl[4];
                        ldsm4(bh, sjc + boff);
                        ldsm4(bl, sjc + 32768 + boff);
                        mma16816(S[2 * ntp],     ah, bh);
                        mma16816(C[2 * ntp],     ah, bl);
                        mma16816(C[2 * ntp],     al, bh);
                        mma16816(S[2 * ntp + 1], ah, bh + 2);
                        mma16816(C[2 * ntp + 1], ah, bl + 2);
                        mma16816(C[2 * ntp + 1], al, bh + 2);
                    }
                }
#pragma unroll
                for (int nt = 0; nt < 8; nt++)
#pragma unroll
                    for (int c = 0; c < 4; c++) S[nt][c] += C[nt][c];

                // ---- masked online softmax ----
                float tmA = -1e30f, tmB = -1e30f;
#pragma unroll
                for (int nt = 0; nt < 8; nt++) {
                    int bp = (h * 64 + nt * 8 + 2 * t) & 31;
                    uint32_t mA = wa[h * 2 + (nt >> 2)] >> bp;
                    uint32_t mB = wb[h * 2 + (nt >> 2)] >> bp;
                    if (mA & 1) tmA = fmaxf(tmA, S[nt][0]);
                    if (mA & 2) tmA = fmaxf(tmA, S[nt][1]);
                    if (mB & 1) tmB = fmaxf(tmB, S[nt][2]);
                    if (mB & 2) tmB = fmaxf(tmB, S[nt][3]);
                }
                tmA = fmaxf(tmA, __shfl_xor_sync(0xffffffffu, tmA, 1));
                tmA = fmaxf(tmA, __shfl_xor_sync(0xffffffffu, tmA, 2));
                tmB = fmaxf(tmB, __shfl_xor_sync(0xffffffffu, tmB, 1));
                tmB = fmaxf(tmB, __shfl_xor_sync(0xffffffffu, tmB, 2));
                float nmA = fmaxf(mr0, tmA), nmB = fmaxf(mr1, tmB);
                float scA = __expf(mr0 - nmA), scB = __expf(mr1 - nmB);
                mr0 = nmA; mr1 = nmB;
                l0 *= scA; l1 *= scB;
#pragma unroll
                for (int ft = 0; ft < 16; ft++) {
                    O[ft][0] *= scA; O[ft][1] *= scA;
                    O[ft][2] *= scB; O[ft][3] *= scB;
                }
                // ---- P = exp(S-m) packed as GEMM2 A-frags ----
                uint32_t phi[16], plo[16];
#pragma unroll
                for (int nt = 0; nt < 8; nt++) {
                    int bp = (h * 64 + nt * 8 + 2 * t) & 31;
                    uint32_t mA = wa[h * 2 + (nt >> 2)] >> bp;
                    uint32_t mB = wb[h * 2 + (nt >> 2)] >> bp;
                    float p0 = (mA & 1) ? __expf(S[nt][0] - mr0) : 0.f;
                    float p1 = (mA & 2) ? __expf(S[nt][1] - mr0) : 0.f;
                    float p2 = (mB & 1) ? __expf(S[nt][2] - mr1) : 0.f;
                    float p3 = (mB & 2) ? __expf(S[nt][3] - mr1) : 0.f;
                    l0 += p0 + p1; l1 += p2 + p3;
                    float h0 = bf16r(p0), h1 = bf16r(p1), h2 = bf16r(p2), h3 = bf16r(p3);
                    int base = (nt >> 1) * 4 + (nt & 1) * 2;
                    phi[base + 0] = packbf(h0, h1);
                    phi[base + 1] = packbf(h2, h3);
                    plo[base + 0] = packbf(p0 - h0, p1 - h1);
                    plo[base + 1] = packbf(p2 - h2, p3 - h3);
                }
                // ---- GEMM2: O += P . Wh_J (ldsm4t pairs two f-blocks) ----
#pragma unroll
                for (int q2 = 0; q2 < 4; q2++) {
                    int brow = h * 64 + q2 * 16 + (lane & 15);
                    uint32_t brb = (uint32_t)brow * 256;
                    uint32_t rot = (uint32_t)(brow & 7) * 16;
#pragma unroll
                    for (int ftp = 0; ftp < 8; ftp++) {
                        uint32_t boff = brb +
                            (((uint32_t)(ftp * 32) + ((lane & 16) ? 16u : 0u)) ^ rot);
                        uint32_t bh[4], bl[4];
                        ldsm4t(bh, sjc + boff);
                        ldsm4t(bl, sjc + 32768 + boff);
                        mma16816(O[2 * ftp],     &phi[q2 * 4], bh);
                        mma16816(O[2 * ftp],     &phi[q2 * 4], bl);
                        mma16816(O[2 * ftp],     &plo[q2 * 4], bh);
                        mma16816(O[2 * ftp + 1], &phi[q2 * 4], bh + 2);
                        mma16816(O[2 * ftp + 1], &phi[q2 * 4], bl + 2);
                        mma16816(O[2 * ftp + 1], &plo[q2 * 4], bh + 2);
                    }
                }
            }
        }
        // ---- epilogue ----
        l0 += __shfl_xor_sync(0xffffffffu, l0, 1);
        l0 += __shfl_xor_sync(0xffffffffu, l0, 2);
        l1 += __shfl_xor_sync(0xffffffffu, l1, 1);
        l1 += __shfl_xor_sync(0xffffffffu, l1, 2);
        int lrowA = m0 + g, lrowB = m0 + 8 + g;
        if (t == 0) {
            d_pm[u * 128 + lrowA] = mr0; d_pl[u * 128 + lrowA] = l0;
            d_pm[u * 128 + lrowB] = mr1; d_pl[u * 128 + lrowB] = l1;
        }
        size_t baseA = ((size_t)u * 128 + lrowA) * FF + 2 * t;
        size_t baseB = ((size_t)u * 128 + lrowB) * FF + 2 * t;
#pragma unroll
        for (int ft = 0; ft < 16; ft++) {
            *(float2*)&d_pO[baseA + ft * 8] = make_float2(O[ft][0], O[ft][1]);
            *(float2*)&d_pO[baseB + ft * 8] = make_float2(O[ft][2], O[ft][3]);
        }
    }
}

// ---------------- combine partials + elu + L2 normalize ----------------
__global__ __launch_bounds__(128) void k_reduce() {
    int rid = blockIdx.x, cnt = d_count;
    if (rid >= cnt) return;
    int tile = rid >> 7, m = rid & 127;
    int f = threadIdx.x;
    int base = tile * JSPLIT;
    float M = -1e30f;
#pragma unroll
    for (int s = 0; s < JSPLIT; s++) M = fmaxf(M, d_pm[(base + s) * 128 + m]);
    float L = 0.f, acc = 0.f;
#pragma unroll 4
    for (int s = 0; s < JSPLIT; s++) {
        float w = __expf(d_pm[(base + s) * 128 + m] - M);
        L += w * d_pl[(base + s) * 128 + m];
        acc += w * d_pO[((size_t)(base + s) * 128 + m) * FF + f];
    }
    float v = acc / L;
    v = (v > 0.f) ? v : expm1f(v);
    __shared__ float red[4];
    float ssq = v * v;
#pragma unroll
    for (int o = 16; o; o >>= 1) ssq += __shfl_xor_sync(0xffffffffu, ssq, o);
    if ((f & 31) == 0) red[f >> 5] = ssq;
    __syncthreads();
    ssq = red[0] + red[1] + red[2] + red[3];
    float inn = 1.f / fmaxf(sqrtf(ssq), 1e-12f);
    d_Hout[(size_t)d_list[rid] * FF + f] = v * inn;
}

__global__ void k_gather(const int* __restrict__ x, float* __restrict__ out) {
    int id = blockIdx.x * blockDim.x + threadIdx.x;
    if (id < BB * 32) {
        int b = id >> 5;
        int c4 = (id & 31) * 4;
        *(float4*)&out[b * FF + c4] = *(const float4*)&d_Hout[(size_t)x[b] * FF + c4];
    }
}

extern "C" void kernel_launch(void* const* d_in, const int* in_sizes, int n_in,
                              void* d_out, int out_size) {
    const int*   x   = (const int*)d_in[0];
    const int*   adj = (const int*)d_in[1];
    const float* emb = (const float*)d_in[2];
    const float* W   = (const float*)d_in[3];
    float* out = (float*)d_out;

    cudaFuncSetAttribute(k_attn, cudaFuncAttributeMaxDynamicSharedMemorySize, SM_TOTAL);

    k_init<<<32, 256>>>();
    k_mark<<<16, 256>>>(x);
    k_compact<<<32, 256>>>();
    k_whgemm<<<128, 256>>>(emb, W);
    k_adjpack<<<4096, 256>>>(adj);
    k_imgJ<<<512, 256>>>();
    k_imgA<<<256, 256>>>();
    k_attn<<<148, 256, SM_TOTAL>>>();
    k_reduce<<<4096, 128>>>();
    k_gather<<<512, 256>>>(x, out);
}

// round 8
// speedup vs baseline: 4.9036x; 1.0605x over previous
#include <cuda_runtime.h>
#include <cuda_bf16.h>
#include <math.h>
#include <stdint.h>

#define NN 8192
#define DD 256
#define FF 128
#define BB 4096
#define JSPLIT 16
#define MAXT 32
#define MAXU (MAXT * JSPLIT)   // 512

#define SA_HI 0
#define SA_LO 32768
#define SJB(b) (65536 + (b) * 65536)
#define SM_TOTAL 196608

// ---------------- device scratch ----------------
__device__ float d_Wh[NN * FF];
__device__ float d_Hout[NN * FF];
__device__ int d_flags[NN], d_list[NN], d_count;
__device__ uint32_t d_adjb[4096 * 256];
__device__ uint4 d_iJh[NN * 16], d_iJl[NN * 16];
__device__ uint4 d_iAh[MAXT * 2048], d_iAl[MAXT * 2048];
__device__ float d_pm[MAXU * 128], d_pl[MAXU * 128];
__device__ float d_pO[(size_t)MAXU * 128 * FF];

// ---------------- helpers ----------------
__device__ __forceinline__ uint32_t smem_u32(const void* p) {
    uint32_t a;
    asm("{ .reg .u64 t; cvta.to.shared.u64 t, %1; cvt.u32.u64 %0, t; }" : "=r"(a) : "l"(p));
    return a;
}
__device__ __forceinline__ float bf16r(float x) {
    return __bfloat162float(__float2bfloat16(x));
}
__device__ __forceinline__ uint32_t packbf(float lo, float hi) {
    uint32_t r;
    asm("cvt.rn.bf16x2.f32 %0, %1, %2;" : "=r"(r) : "f"(hi), "f"(lo));
    return r;
}
__device__ __forceinline__ void split8(const float* v, uint4& h, uint4& l) {
    uint32_t hw[4], lw[4];
#pragma unroll
    for (int p = 0; p < 4; p++) {
        float a = v[2 * p], b = v[2 * p + 1];
        float ah = bf16r(a), bh = bf16r(b);
        hw[p] = packbf(ah, bh);
        lw[p] = packbf(a - ah, b - bh);
    }
    h = make_uint4(hw[0], hw[1], hw[2], hw[3]);
    l = make_uint4(lw[0], lw[1], lw[2], lw[3]);
}
__device__ __forceinline__ void ldsm4(uint32_t* r, uint32_t addr) {
    asm volatile("ldmatrix.sync.aligned.m8n8.x4.shared.b16 {%0,%1,%2,%3}, [%4];"
                 : "=r"(r[0]), "=r"(r[1]), "=r"(r[2]), "=r"(r[3]) : "r"(addr));
}
__device__ __forceinline__ void ldsm4t(uint32_t* r, uint32_t addr) {
    asm volatile("ldmatrix.sync.aligned.m8n8.x4.trans.shared.b16 {%0,%1,%2,%3}, [%4];"
                 : "=r"(r[0]), "=r"(r[1]), "=r"(r[2]), "=r"(r[3]) : "r"(addr));
}
__device__ __forceinline__ void mma16816(float* d, const uint32_t* a, const uint32_t* b) {
    asm volatile("mma.sync.aligned.m16n8k16.row.col.f32.bf16.bf16.f32 "
                 "{%0,%1,%2,%3}, {%4,%5,%6,%7}, {%8,%9}, {%0,%1,%2,%3};"
                 : "+f"(d[0]), "+f"(d[1]), "+f"(d[2]), "+f"(d[3])
                 : "r"(a[0]), "r"(a[1]), "r"(a[2]), "r"(a[3]), "r"(b[0]), "r"(b[1]));
}
#define CPA(dst, src) \
    asm volatile("cp.async.cg.shared.global [%0], [%1], 16;" :: "r"(dst), "l"(src))
#define CPC() asm volatile("cp.async.commit_group;" ::: "memory")
#define CPW(n) asm volatile("cp.async.wait_group %0;" :: "n"(n) : "memory")

// ---------------- setup kernels ----------------
__global__ void k_init() {
    int i = blockIdx.x * blockDim.x + threadIdx.x;
    if (i < NN) d_flags[i] = 0;
    if (i == 0) d_count = 0;
}
__global__ void k_mark(const int* __restrict__ x) {
    int i = blockIdx.x * blockDim.x + threadIdx.x;
    if (i < BB) d_flags[x[i]] = 1;
}
__global__ void k_compact() {
    int i = blockIdx.x * blockDim.x + threadIdx.x;
    if (i < NN && d_flags[i]) {
        int p = atomicAdd(&d_count, 1);
        d_list[p] = i;
    }
}

// ---------------- Wh = embedding @ W  (32-row tiles, 256 CTAs) ----------------
__global__ __launch_bounds__(256) void k_whgemm(const float* __restrict__ emb,
                                                const float* __restrict__ W) {
    __shared__ float At[32][36];   // [k][m], pad 32->36
    __shared__ float Bs[32][128];  // [k][f]
    int tid = threadIdx.x, tx = tid & 31, ty = tid >> 5;  // ty 0..7
    int row0 = blockIdx.x * 32;
    float acc[4][4];
#pragma unroll
    for (int r = 0; r < 4; r++)
#pragma unroll
        for (int c = 0; c < 4; c++) acc[r][c] = 0.f;

    for (int k0 = 0; k0 < DD; k0 += 32) {
        {
            int r = tid >> 3, c4 = (tid & 7) * 4;
            float4 v = *(const float4*)&emb[(row0 + r) * DD + k0 + c4];
            At[c4 + 0][r] = v.x; At[c4 + 1][r] = v.y;
            At[c4 + 2][r] = v.z; At[c4 + 3][r] = v.w;
        }
#pragma unroll
        for (int it = 0; it < 4; it++) {
            int id = it * 256 + tid;
            int r = id >> 5, c4 = (id & 31) * 4;
            *(float4*)&Bs[r][c4] = *(const float4*)&W[(k0 + r) * FF + c4];
        }
        __syncthreads();
#pragma unroll
        for (int k = 0; k < 32; k++) {
            float4 a = *(const float4*)&At[k][4 * ty];
            float4 b = *(const float4*)&Bs[k][4 * tx];
            float av[4] = {a.x, a.y, a.z, a.w};
            float bv[4] = {b.x, b.y, b.z, b.w};
#pragma unroll
            for (int r = 0; r < 4; r++)
#pragma unroll
                for (int c = 0; c < 4; c++) acc[r][c] += av[r] * bv[c];
        }
        __syncthreads();
    }
#pragma unroll
    for (int r = 0; r < 4; r++)
        *(float4*)&d_Wh[(row0 + 4 * ty + r) * FF + 4 * tx] =
            make_float4(acc[r][0], acc[r][1], acc[r][2], acc[r][3]);
}

// ---------------- image builders ----------------
__global__ void k_imgJ() {
    int idx = blockIdx.x * 256 + threadIdx.x;
    int row = idx >> 4, c = idx & 15;
    float v[8];
    *(float4*)&v[0] = *(const float4*)&d_Wh[(size_t)row * FF + c * 8];
    *(float4*)&v[4] = *(const float4*)&d_Wh[(size_t)row * FF + c * 8 + 4];
    uint4 h, l; split8(v, h, l);
    d_iJh[idx] = h; d_iJl[idx] = l;
}
__global__ void k_imgA() {
    int idx = blockIdx.x * 256 + threadIdx.x;
    int tile = idx >> 11, gc = idx & 2047;
    int cnt = d_count;
    if (tile >= (cnt + 127) >> 7) return;
    int row = gc >> 4, c = gc & 15;
    int ridx = tile * 128 + row; if (ridx >= cnt) ridx = cnt - 1;
    const float* src = &d_Wh[(size_t)d_list[ridx] * FF + c * 8];
    float v[8];
    *(float4*)&v[0] = *(const float4*)&src[0];
    *(float4*)&v[4] = *(const float4*)&src[4];
    uint4 h, l; split8(v, h, l);
    d_iAh[idx] = h; d_iAl[idx] = l;
}
__global__ __launch_bounds__(256) void k_adjpack(const int* __restrict__ adj) {
    int row = blockIdx.x;
    if (row >= d_count) return;
    size_t grow = (size_t)d_list[row] * NN;
    int tid = threadIdx.x, lane = tid & 31;
#pragma unroll 4
    for (int it = 0; it < 32; it++) {
        int j = it * 256 + tid;
        uint32_t bal = __ballot_sync(0xffffffffu, adj[grow + j] != 0);
        if (lane == 0) d_adjb[row * 256 + (j >> 5)] = bal;
    }
}

// ---------------- mma.sync fused attention (pipelined) ----------------
__global__ __launch_bounds__(256, 1) void k_attn() {
    extern __shared__ char smc[];
    uint32_t smb = smem_u32(smc);
    const int tid = threadIdx.x, wid = tid >> 5, lane = tid & 31;
    const int g = lane >> 2, t = lane & 3;
    const int m0 = wid * 16;
    const int cnt = d_count;
    const int ntiles = (cnt + 127) >> 7;
    const int nunits = ntiles * JSPLIT;

    const int arow = m0 + (lane & 15);
    const uint32_t acolx = (lane & 16) ? 16u : 0u;
    const uint32_t abase = smb + (uint32_t)arow * 256;
    const uint32_t arot = (uint32_t)(arow & 7) * 16;

    uint32_t stoff[8];
#pragma unroll
    for (int s = 0; s < 8; s++) {
        int idx = s * 256 + tid;
        int row = idx >> 4, c = idx & 15;
        stoff[s] = (uint32_t)row * 256 + (((uint32_t)c * 16) ^ ((row & 7) * 16));
    }

    for (int u = blockIdx.x; u < nunits; u += gridDim.x) {
        const int tile = u >> 4, sl = u & 15;
        __syncthreads();

        {
            const uint4* gah = &d_iAh[tile * 2048];
            const uint4* gal = &d_iAl[tile * 2048];
            const uint4* gjh = &d_iJh[(sl * 512) * 16];
            const uint4* gjl = &d_iJl[(sl * 512) * 16];
#pragma unroll
            for (int s = 0; s < 8; s++) {
                int idx = s * 256 + tid;
                CPA(smb + SA_HI + stoff[s], gah + idx);
                CPA(smb + SA_LO + stoff[s], gal + idx);
                CPA(smb + SJB(0) + stoff[s], gjh + idx);
                CPA(smb + SJB(0) + 32768 + stoff[s], gjl + idx);
            }
            CPC();
        }

        int rA = tile * 128 + m0 + g;
        int rB = rA + 8;
        int rAc = rA < cnt ? rA : cnt - 1;
        int rBc = rB < cnt ? rB : cnt - 1;

        float O[16][4];
#pragma unroll
        for (int ft = 0; ft < 16; ft++)
            O[ft][0] = O[ft][1] = O[ft][2] = O[ft][3] = 0.f;
        float mr0 = -1e30f, mr1 = -1e30f, l0 = 0.f, l1 = 0.f;

#pragma unroll 1
        for (int jt = 0; jt < 4; jt++) {
            const int j0 = sl * 512 + jt * 128;
            const uint32_t sjc = smb + SJB(jt & 1);

            if (jt > 0) __syncthreads();
            if (jt < 3) {
                const uint4* gjh = &d_iJh[(j0 + 128) * 16];
                const uint4* gjl = &d_iJl[(j0 + 128) * 16];
                uint32_t sjn = smb + SJB((jt + 1) & 1);
#pragma unroll
                for (int s = 0; s < 8; s++) {
                    int idx = s * 256 + tid;
                    CPA(sjn + stoff[s], gjh + idx);
                    CPA(sjn + 32768 + stoff[s], gjl + idx);
                }
                CPC();
                CPW(1);
            } else {
                CPW(0);
            }
            __syncthreads();

            uint4 awA = *(const uint4*)&d_adjb[rAc * 256 + (j0 >> 5)];
            uint4 awB = *(const uint4*)&d_adjb[rBc * 256 + (j0 >> 5)];
            const uint32_t* wa = &awA.x;
            const uint32_t* wb = &awB.x;

#pragma unroll
            for (int h = 0; h < 2; h++) {
                // ---- GEMM1: S(hi.hi) + C(cross) independent chains ----
                float S[8][4], C[8][4];
#pragma unroll
                for (int nt = 0; nt < 8; nt++)
#pragma unroll
                    for (int c = 0; c < 4; c++) { S[nt][c] = 0.f; C[nt][c] = 0.f; }
#pragma unroll 2
                for (int q = 0; q < 8; q++) {
                    uint32_t ah[4], al[4];
                    uint32_t aoff = ((uint32_t)(q * 32) + acolx) ^ arot;
                    ldsm4(ah, abase + SA_HI + aoff);
                    ldsm4(al, abase + SA_LO + aoff);
#pragma unroll
                    for (int ntp = 0; ntp < 4; ntp++) {
                        int brow = h * 64 + ntp * 16 + ((lane >> 4) & 1) * 8 + (lane & 7);
                        uint32_t boff = (uint32_t)brow * 256 +
                            (((uint32_t)(q * 32) + ((lane & 8) ? 16u : 0u)) ^ ((brow & 7) * 16));
                        uint32_t bh[4], bl[4];
                        ldsm4(bh, sjc + boff);
                        ldsm4(bl, sjc + 32768 + boff);
                        mma16816(S[2 * ntp],     ah, bh);
                        mma16816(C[2 * ntp],     ah, bl);
                        mma16816(C[2 * ntp],     al, bh);
                        mma16816(S[2 * ntp + 1], ah, bh + 2);
                        mma16816(C[2 * ntp + 1], ah, bl + 2);
                        mma16816(C[2 * ntp + 1], al, bh + 2);
                    }
                }
#pragma unroll
                for (int nt = 0; nt < 8; nt++)
#pragma unroll
                    for (int c = 0; c < 4; c++) S[nt][c] += C[nt][c];

                // ---- masked online softmax ----
                float tmA = -1e30f, tmB = -1e30f;
#pragma unroll
                for (int nt = 0; nt < 8; nt++) {
                    int bp = (h * 64 + nt * 8 + 2 * t) & 31;
                    uint32_t mA = wa[h * 2 + (nt >> 2)] >> bp;
                    uint32_t mB = wb[h * 2 + (nt >> 2)] >> bp;
                    if (mA & 1) tmA = fmaxf(tmA, S[nt][0]);
                    if (mA & 2) tmA = fmaxf(tmA, S[nt][1]);
                    if (mB & 1) tmB = fmaxf(tmB, S[nt][2]);
                    if (mB & 2) tmB = fmaxf(tmB, S[nt][3]);
                }
                tmA = fmaxf(tmA, __shfl_xor_sync(0xffffffffu, tmA, 1));
                tmA = fmaxf(tmA, __shfl_xor_sync(0xffffffffu, tmA, 2));
                tmB = fmaxf(tmB, __shfl_xor_sync(0xffffffffu, tmB, 1));
                tmB = fmaxf(tmB, __shfl_xor_sync(0xffffffffu, tmB, 2));
                float nmA = fmaxf(mr0, tmA), nmB = fmaxf(mr1, tmB);
                float scA = __expf(mr0 - nmA), scB = __expf(mr1 - nmB);
                mr0 = nmA; mr1 = nmB;
                l0 *= scA; l1 *= scB;
#pragma unroll
                for (int ft = 0; ft < 16; ft++) {
                    O[ft][0] *= scA; O[ft][1] *= scA;
                    O[ft][2] *= scB; O[ft][3] *= scB;
                }
                // ---- P = exp(S-m), bf16-packed as GEMM2 A-frags (hi only) ----
                uint32_t phi[16];
#pragma unroll
                for (int nt = 0; nt < 8; nt++) {
                    int bp = (h * 64 + nt * 8 + 2 * t) & 31;
                    uint32_t mA = wa[h * 2 + (nt >> 2)] >> bp;
                    uint32_t mB = wb[h * 2 + (nt >> 2)] >> bp;
                    float p0 = (mA & 1) ? __expf(S[nt][0] - mr0) : 0.f;
                    float p1 = (mA & 2) ? __expf(S[nt][1] - mr0) : 0.f;
                    float p2 = (mB & 1) ? __expf(S[nt][2] - mr1) : 0.f;
                    float p3 = (mB & 2) ? __expf(S[nt][3] - mr1) : 0.f;
                    l0 += p0 + p1; l1 += p2 + p3;
                    int base = (nt >> 1) * 4 + (nt & 1) * 2;
                    phi[base + 0] = packbf(p0, p1);
                    phi[base + 1] = packbf(p2, p3);
                }
                // ---- GEMM2 (2-pass): O += P_bf16 . (J_hi + J_lo) ----
#pragma unroll
                for (int q2 = 0; q2 < 4; q2++) {
                    int brow = h * 64 + q2 * 16 + (lane & 15);
                    uint32_t brb = (uint32_t)brow * 256;
                    uint32_t rot = (uint32_t)(brow & 7) * 16;
#pragma unroll
                    for (int ftp = 0; ftp < 8; ftp++) {
                        uint32_t boff = brb +
                            (((uint32_t)(ftp * 32) + ((lane & 16) ? 16u : 0u)) ^ rot);
                        uint32_t bh[4], bl[4];
                        ldsm4t(bh, sjc + boff);
                        ldsm4t(bl, sjc + 32768 + boff);
                        mma16816(O[2 * ftp],     &phi[q2 * 4], bh);
                        mma16816(O[2 * ftp],     &phi[q2 * 4], bl);
                        mma16816(O[2 * ftp + 1], &phi[q2 * 4], bh + 2);
                        mma16816(O[2 * ftp + 1], &phi[q2 * 4], bl + 2);
                    }
                }
            }
        }
        // ---- epilogue ----
        l0 += __shfl_xor_sync(0xffffffffu, l0, 1);
        l0 += __shfl_xor_sync(0xffffffffu, l0, 2);
        l1 += __shfl_xor_sync(0xffffffffu, l1, 1);
        l1 += __shfl_xor_sync(0xffffffffu, l1, 2);
        int lrowA = m0 + g, lrowB = m0 + 8 + g;
        if (t == 0) {
            d_pm[u * 128 + lrowA] = mr0; d_pl[u * 128 + lrowA] = l0;
            d_pm[u * 128 + lrowB] = mr1; d_pl[u * 128 + lrowB] = l1;
        }
        size_t baseA = ((size_t)u * 128 + lrowA) * FF + 2 * t;
        size_t baseB = ((size_t)u * 128 + lrowB) * FF + 2 * t;
#pragma unroll
        for (int ft = 0; ft < 16; ft++) {
            *(float2*)&d_pO[baseA + ft * 8] = make_float2(O[ft][0], O[ft][1]);
            *(float2*)&d_pO[baseB + ft * 8] = make_float2(O[ft][2], O[ft][3]);
        }
    }
}

// ---------------- combine partials + elu + L2 normalize ----------------
__global__ __launch_bounds__(128) void k_reduce() {
    int rid = blockIdx.x, cnt = d_count;
    if (rid >= cnt) return;
    int tile = rid >> 7, m = rid & 127;
    int f = threadIdx.x;
    int base = tile * JSPLIT;
    float M = -1e30f;
#pragma unroll
    for (int s = 0; s < JSPLIT; s++) M = fmaxf(M, d_pm[(base + s) * 128 + m]);
    float L = 0.f, acc = 0.f;
#pragma unroll 4
    for (int s = 0; s < JSPLIT; s++) {
        float w = __expf(d_pm[(base + s) * 128 + m] - M);
        L += w * d_pl[(base + s) * 128 + m];
        acc += w * d_pO[((size_t)(base + s) * 128 + m) * FF + f];
    }
    float v = acc / L;
    v = (v > 0.f) ? v : expm1f(v);
    __shared__ float red[4];
    float ssq = v * v;
#pragma unroll
    for (int o = 16; o; o >>= 1) ssq += __shfl_xor_sync(0xffffffffu, ssq, o);
    if ((f & 31) == 0) red[f >> 5] = ssq;
    __syncthreads();
    ssq = red[0] + red[1] + red[2] + red[3];
    float inn = 1.f / fmaxf(sqrtf(ssq), 1e-12f);
    d_Hout[(size_t)d_list[rid] * FF + f] = v * inn;
}

__global__ void k_gather(const int* __restrict__ x, float* __restrict__ out) {
    int id = blockIdx.x * blockDim.x + threadIdx.x;
    if (id < BB * 32) {
        int b = id >> 5;
        int c4 = (id & 31) * 4;
        *(float4*)&out[b * FF + c4] = *(const float4*)&d_Hout[(size_t)x[b] * FF + c4];
    }
}

extern "C" void kernel_launch(void* const* d_in, const int* in_sizes, int n_in,
                              void* d_out, int out_size) {
    const int*   x   = (const int*)d_in[0];
    const int*   adj = (const int*)d_in[1];
    const float* emb = (const float*)d_in[2];
    const float* W   = (const float*)d_in[3];
    float* out = (float*)d_out;

    cudaFuncSetAttribute(k_attn, cudaFuncAttributeMaxDynamicSharedMemorySize, SM_TOTAL);

    k_init<<<32, 256>>>();
    k_mark<<<16, 256>>>(x);
    k_compact<<<32, 256>>>();
    k_whgemm<<<256, 256>>>(emb, W);
    k_adjpack<<<4096, 256>>>(adj);
    k_imgJ<<<512, 256>>>();
    k_imgA<<<256, 256>>>();
    k_attn<<<148, 256, SM_TOTAL>>>();
    k_reduce<<<4096, 128>>>();
    k_gather<<<512, 256>>>(x, out);
}

// round 10
// speedup vs baseline: 5.2213x; 1.0648x over previous
#include <cuda_runtime.h>
#include <cuda_fp16.h>
#include <math.h>
#include <stdint.h>

#define NN 8192
#define DD 256
#define FF 128
#define BB 4096
#define JSPLIT 16
#define MAXT 32
#define MAXU (MAXT * JSPLIT)   // 512

#define SA_HI 0
#define SA_LO 32768
#define SJB(b) (65536 + (b) * 65536)
#define SM_TOTAL 196608

// ---------------- device scratch ----------------
__device__ float d_Wh[NN * FF];
__device__ float d_Hout[NN * FF];
__device__ int d_flags[NN], d_list[NN], d_count;
__device__ uint32_t d_adjb[4096 * 256];
__device__ uint4 d_iJh[NN * 16], d_iJl[NN * 16];     // Wh fp16 hi/lo [j][f]
__device__ uint4 d_iAh[MAXT * 2048], d_iAl[MAXT * 2048];
__device__ float d_pm[MAXU * 128], d_pl[MAXU * 128];
__device__ float d_pO[(size_t)MAXU * 128 * FF];

// ---------------- helpers ----------------
__device__ __forceinline__ uint32_t smem_u32(const void* p) {
    uint32_t a;
    asm("{ .reg .u64 t; cvta.to.shared.u64 t, %1; cvt.u32.u64 %0, t; }" : "=r"(a) : "l"(p));
    return a;
}
__device__ __forceinline__ float f16r(float x) {
    return __half2float(__float2half_rn(x));
}
__device__ __forceinline__ uint32_t packhf(float lo, float hi) {
    __half2 h = __floats2half2_rn(lo, hi);   // .x = lo (low 16 bits)
    return *(uint32_t*)&h;
}
__device__ __forceinline__ void split8(const float* v, uint4& h, uint4& l) {
    uint32_t hw[4], lw[4];
#pragma unroll
    for (int p = 0; p < 4; p++) {
        float a = v[2 * p], b = v[2 * p + 1];
        hw[p] = packhf(a, b);
        lw[p] = packhf(a - f16r(a), b - f16r(b));
    }
    h = make_uint4(hw[0], hw[1], hw[2], hw[3]);
    l = make_uint4(lw[0], lw[1], lw[2], lw[3]);
}
__device__ __forceinline__ void ldsm4(uint32_t* r, uint32_t addr) {
    asm volatile("ldmatrix.sync.aligned.m8n8.x4.shared.b16 {%0,%1,%2,%3}, [%4];"
                 : "=r"(r[0]), "=r"(r[1]), "=r"(r[2]), "=r"(r[3]) : "r"(addr));
}
__device__ __forceinline__ void ldsm4t(uint32_t* r, uint32_t addr) {
    asm volatile("ldmatrix.sync.aligned.m8n8.x4.trans.shared.b16 {%0,%1,%2,%3}, [%4];"
                 : "=r"(r[0]), "=r"(r[1]), "=r"(r[2]), "=r"(r[3]) : "r"(addr));
}
__device__ __forceinline__ void mma16816(float* d, const uint32_t* a, const uint32_t* b) {
    asm volatile("mma.sync.aligned.m16n8k16.row.col.f32.f16.f16.f32 "
                 "{%0,%1,%2,%3}, {%4,%5,%6,%7}, {%8,%9}, {%0,%1,%2,%3};"
                 : "+f"(d[0]), "+f"(d[1]), "+f"(d[2]), "+f"(d[3])
                 : "r"(a[0]), "r"(a[1]), "r"(a[2]), "r"(a[3]), "r"(b[0]), "r"(b[1]));
}
#define CPA(dst, src) \
    asm volatile("cp.async.cg.shared.global [%0], [%1], 16;" :: "r"(dst), "l"(src))
#define CPC() asm volatile("cp.async.commit_group;" ::: "memory")
#define CPW(n) asm volatile("cp.async.wait_group %0;" :: "n"(n) : "memory")

// ---------------- setup kernels ----------------
__global__ void k_init() {
    int i = blockIdx.x * blockDim.x + threadIdx.x;
    if (i < NN) d_flags[i] = 0;
    if (i == 0) d_count = 0;
}
__global__ void k_mark(const int* __restrict__ x) {
    int i = blockIdx.x * blockDim.x + threadIdx.x;
    if (i < BB) d_flags[x[i]] = 1;
}
__global__ void k_compact() {
    int i = blockIdx.x * blockDim.x + threadIdx.x;
    if (i < NN && d_flags[i]) {
        int p = atomicAdd(&d_count, 1);
        d_list[p] = i;
    }
}

// ---------------- Wh = embedding @ W  (32-row tiles, 256 CTAs) ----------------
__global__ __launch_bounds__(256) void k_whgemm(const float* __restrict__ emb,
                                                const float* __restrict__ W) {
    __shared__ float At[32][36];
    __shared__ float Bs[32][128];
    int tid = threadIdx.x, tx = tid & 31, ty = tid >> 5;
    int row0 = blockIdx.x * 32;
    float acc[4][4];
#pragma unroll
    for (int r = 0; r < 4; r++)
#pragma unroll
        for (int c = 0; c < 4; c++) acc[r][c] = 0.f;

    for (int k0 = 0; k0 < DD; k0 += 32) {
        {
            int r = tid >> 3, c4 = (tid & 7) * 4;
            float4 v = *(const float4*)&emb[(row0 + r) * DD + k0 + c4];
            At[c4 + 0][r] = v.x; At[c4 + 1][r] = v.y;
            At[c4 + 2][r] = v.z; At[c4 + 3][r] = v.w;
        }
#pragma unroll
        for (int it = 0; it < 4; it++) {
            int id = it * 256 + tid;
            int r = id >> 5, c4 = (id & 31) * 4;
            *(float4*)&Bs[r][c4] = *(const float4*)&W[(k0 + r) * FF + c4];
        }
        __syncthreads();
#pragma unroll
        for (int k = 0; k < 32; k++) {
            float4 a = *(const float4*)&At[k][4 * ty];
            float4 b = *(const float4*)&Bs[k][4 * tx];
            float av[4] = {a.x, a.y, a.z, a.w};
            float bv[4] = {b.x, b.y, b.z, b.w};
#pragma unroll
            for (int r = 0; r < 4; r++)
#pragma unroll
                for (int c = 0; c < 4; c++) acc[r][c] += av[r] * bv[c];
        }
        __syncthreads();
    }
#pragma unroll
    for (int r = 0; r < 4; r++)
        *(float4*)&d_Wh[(row0 + 4 * ty + r) * FF + 4 * tx] =
            make_float4(acc[r][0], acc[r][1], acc[r][2], acc[r][3]);
}

// ---------------- image builders ----------------
__global__ void k_imgJ() {
    int idx = blockIdx.x * 256 + threadIdx.x;
    int row = idx >> 4, c = idx & 15;
    float v[8];
    *(float4*)&v[0] = *(const float4*)&d_Wh[(size_t)row * FF + c * 8];
    *(float4*)&v[4] = *(const float4*)&d_Wh[(size_t)row * FF + c * 8 + 4];
    uint4 h, l; split8(v, h, l);
    d_iJh[idx] = h; d_iJl[idx] = l;
}
__global__ void k_imgA() {
    int idx = blockIdx.x * 256 + threadIdx.x;
    int tile = idx >> 11, gc = idx & 2047;
    int cnt = d_count;
    if (tile >= (cnt + 127) >> 7) return;
    int row = gc >> 4, c = gc & 15;
    int ridx = tile * 128 + row; if (ridx >= cnt) ridx = cnt - 1;
    const float* src = &d_Wh[(size_t)d_list[ridx] * FF + c * 8];
    float v[8];
    *(float4*)&v[0] = *(const float4*)&src[0];
    *(float4*)&v[4] = *(const float4*)&src[4];
    uint4 h, l; split8(v, h, l);
    d_iAh[idx] = h; d_iAl[idx] = l;
}
__global__ __launch_bounds__(256) void k_adjpack(const int* __restrict__ adj) {
    int row = blockIdx.x;
    if (row >= d_count) return;
    size_t grow = (size_t)d_list[row] * NN;
    int tid = threadIdx.x, lane = tid & 31;
#pragma unroll 4
    for (int it = 0; it < 32; it++) {
        int j = it * 256 + tid;
        uint32_t bal = __ballot_sync(0xffffffffu, adj[grow + j] != 0);
        if (lane == 0) d_adjb[row * 256 + (j >> 5)] = bal;
    }
}

// ---------------- mma.sync fused attention (fp16 emulation) ----------------
__global__ __launch_bounds__(256, 1) void k_attn() {
    extern __shared__ char smc[];
    uint32_t smb = smem_u32(smc);
    const int tid = threadIdx.x, wid = tid >> 5, lane = tid & 31;
    const int g = lane >> 2, t = lane & 3;
    const int m0 = wid * 16;
    const int cnt = d_count;
    const int ntiles = (cnt + 127) >> 7;
    const int nunits = ntiles * JSPLIT;

    const int arow = m0 + (lane & 15);
    const uint32_t acolx = (lane & 16) ? 16u : 0u;
    const uint32_t abase = smb + (uint32_t)arow * 256;
    const uint32_t arot = (uint32_t)(arow & 7) * 16;

    uint32_t stoff[8];
#pragma unroll
    for (int s = 0; s < 8; s++) {
        int idx = s * 256 + tid;
        int row = idx >> 4, c = idx & 15;
        stoff[s] = (uint32_t)row * 256 + (((uint32_t)c * 16) ^ ((row & 7) * 16));
    }

    for (int u = blockIdx.x; u < nunits; u += gridDim.x) {
        const int tile = u >> 4, sl = u & 15;
        __syncthreads();

        {
            const uint4* gah = &d_iAh[tile * 2048];
            const uint4* gal = &d_iAl[tile * 2048];
            const uint4* gjh = &d_iJh[(sl * 512) * 16];
            const uint4* gjl = &d_iJl[(sl * 512) * 16];
#pragma unroll
            for (int s = 0; s < 8; s++) {
                int idx = s * 256 + tid;
                CPA(smb + SA_HI + stoff[s], gah + idx);
                CPA(smb + SA_LO + stoff[s], gal + idx);
                CPA(smb + SJB(0) + stoff[s], gjh + idx);
                CPA(smb + SJB(0) + 32768 + stoff[s], gjl + idx);
            }
            CPC();
        }

        int rA = tile * 128 + m0 + g;
        int rB = rA + 8;
        int rAc = rA < cnt ? rA : cnt - 1;
        int rBc = rB < cnt ? rB : cnt - 1;

        float O[16][4];
#pragma unroll
        for (int ft = 0; ft < 16; ft++)
            O[ft][0] = O[ft][1] = O[ft][2] = O[ft][3] = 0.f;
        float mr0 = -1e30f, mr1 = -1e30f, l0 = 0.f, l1 = 0.f;

        uint32_t ahr[32];   // A_hi fragments, persistent for the whole unit

#pragma unroll 1
        for (int jt = 0; jt < 4; jt++) {
            const int j0 = sl * 512 + jt * 128;
            const uint32_t sjc = smb + SJB(jt & 1);

            if (jt > 0) __syncthreads();
            if (jt < 3) {
                const uint4* gjh = &d_iJh[(j0 + 128) * 16];
                const uint4* gjl = &d_iJl[(j0 + 128) * 16];
                uint32_t sjn = smb + SJB((jt + 1) & 1);
#pragma unroll
                for (int s = 0; s < 8; s++) {
                    int idx = s * 256 + tid;
                    CPA(sjn + stoff[s], gjh + idx);
                    CPA(sjn + 32768 + stoff[s], gjl + idx);
                }
                CPC();
                CPW(1);
            } else {
                CPW(0);
            }
            __syncthreads();

            if (jt == 0) {   // load persistent A_hi fragments once
#pragma unroll
                for (int q = 0; q < 8; q++) {
                    uint32_t aoff = ((uint32_t)(q * 32) + acolx) ^ arot;
                    ldsm4(&ahr[4 * q], abase + SA_HI + aoff);
                }
            }

            uint4 awA = *(const uint4*)&d_adjb[rAc * 256 + (j0 >> 5)];
            uint4 awB = *(const uint4*)&d_adjb[rBc * 256 + (j0 >> 5)];
            const uint32_t* wa = &awA.x;
            const uint32_t* wb = &awB.x;

#pragma unroll
            for (int h = 0; h < 2; h++) {
                // ---- GEMM1 (3-pass fp16): S(hi.hi) + C(cross) ----
                float S[8][4], C[8][4];
#pragma unroll
                for (int nt = 0; nt < 8; nt++)
#pragma unroll
                    for (int c = 0; c < 4; c++) { S[nt][c] = 0.f; C[nt][c] = 0.f; }
#pragma unroll 2
                for (int q = 0; q < 8; q++) {
                    uint32_t al[4];
                    uint32_t aoff = ((uint32_t)(q * 32) + acolx) ^ arot;
                    ldsm4(al, abase + SA_LO + aoff);
                    const uint32_t* ah = &ahr[4 * q];
#pragma unroll
                    for (int ntp = 0; ntp < 4; ntp++) {
                        int brow = h * 64 + ntp * 16 + ((lane >> 4) & 1) * 8 + (lane & 7);
                        uint32_t boff = (uint32_t)brow * 256 +
                            (((uint32_t)(q * 32) + ((lane & 8) ? 16u : 0u)) ^ ((brow & 7) * 16));
                        uint32_t bh[4], bl[4];
                        ldsm4(bh, sjc + boff);
                        ldsm4(bl, sjc + 32768 + boff);
                        mma16816(S[2 * ntp],     ah, bh);
                        mma16816(C[2 * ntp],     ah, bl);
                        mma16816(C[2 * ntp],     al, bh);
                        mma16816(S[2 * ntp + 1], ah, bh + 2);
                        mma16816(C[2 * ntp + 1], ah, bl + 2);
                        mma16816(C[2 * ntp + 1], al, bh + 2);
                    }
                }
#pragma unroll
                for (int nt = 0; nt < 8; nt++)
#pragma unroll
                    for (int c = 0; c < 4; c++) S[nt][c] += C[nt][c];

                // ---- masked online softmax ----
                float tmA = -1e30f, tmB = -1e30f;
#pragma unroll
                for (int nt = 0; nt < 8; nt++) {
                    int bp = (h * 64 + nt * 8 + 2 * t) & 31;
                    uint32_t mA = wa[h * 2 + (nt >> 2)] >> bp;
                    uint32_t mB = wb[h * 2 + (nt >> 2)] >> bp;
                    if (mA & 1) tmA = fmaxf(tmA, S[nt][0]);
                    if (mA & 2) tmA = fmaxf(tmA, S[nt][1]);
                    if (mB & 1) tmB = fmaxf(tmB, S[nt][2]);
                    if (mB & 2) tmB = fmaxf(tmB, S[nt][3]);
                }
                tmA = fmaxf(tmA, __shfl_xor_sync(0xffffffffu, tmA, 1));
                tmA = fmaxf(tmA, __shfl_xor_sync(0xffffffffu, tmA, 2));
                tmB = fmaxf(tmB, __shfl_xor_sync(0xffffffffu, tmB, 1));
                tmB = fmaxf(tmB, __shfl_xor_sync(0xffffffffu, tmB, 2));
                float nmA = fmaxf(mr0, tmA), nmB = fmaxf(mr1, tmB);
                float scA = __expf(mr0 - nmA), scB = __expf(mr1 - nmB);
                mr0 = nmA; mr1 = nmB;
                l0 *= scA; l1 *= scB;
#pragma unroll
                for (int ft = 0; ft < 16; ft++) {
                    O[ft][0] *= scA; O[ft][1] *= scA;
                    O[ft][2] *= scB; O[ft][3] *= scB;
                }
                // ---- P = exp(S-m), fp16-packed as GEMM2 A-frags ----
                uint32_t phi[16];
#pragma unroll
                for (int nt = 0; nt < 8; nt++) {
                    int bp = (h * 64 + nt * 8 + 2 * t) & 31;
                    uint32_t mA = wa[h * 2 + (nt >> 2)] >> bp;
                    uint32_t mB = wb[h * 2 + (nt >> 2)] >> bp;
                    float p0 = (mA & 1) ? __expf(S[nt][0] - mr0) : 0.f;
                    float p1 = (mA & 2) ? __expf(S[nt][1] - mr0) : 0.f;
                    float p2 = (mB & 1) ? __expf(S[nt][2] - mr1) : 0.f;
                    float p3 = (mB & 2) ? __expf(S[nt][3] - mr1) : 0.f;
                    l0 += p0 + p1; l1 += p2 + p3;
                    int base = (nt >> 1) * 4 + (nt & 1) * 2;
                    phi[base + 0] = packhf(p0, p1);
                    phi[base + 1] = packhf(p2, p3);
                }
                // ---- GEMM2 (1-pass fp16): O += P . J_hi ----
#pragma unroll
                for (int q2 = 0; q2 < 4; q2++) {
                    int brow = h * 64 + q2 * 16 + (lane & 15);
                    uint32_t brb = (uint32_t)brow * 256;
                    uint32_t rot = (uint32_t)(brow & 7) * 16;
#pragma unroll
                    for (int ftp = 0; ftp < 8; ftp++) {
                        uint32_t boff = brb +
                            (((uint32_t)(ftp * 32) + ((lane & 16) ? 16u : 0u)) ^ rot);
                        uint32_t bh[4];
                        ldsm4t(bh, sjc + boff);
                        mma16816(O[2 * ftp],     &phi[q2 * 4], bh);
                        mma16816(O[2 * ftp + 1], &phi[q2 * 4], bh + 2);
                    }
                }
            }
        }
        // ---- epilogue ----
        l0 += __shfl_xor_sync(0xffffffffu, l0, 1);
        l0 += __shfl_xor_sync(0xffffffffu, l0, 2);
        l1 += __shfl_xor_sync(0xffffffffu, l1, 1);
        l1 += __shfl_xor_sync(0xffffffffu, l1, 2);
        int lrowA = m0 + g, lrowB = m0 + 8 + g;
        if (t == 0) {
            d_pm[u * 128 + lrowA] = mr0; d_pl[u * 128 + lrowA] = l0;
            d_pm[u * 128 + lrowB] = mr1; d_pl[u * 128 + lrowB] = l1;
        }
        size_t baseA = ((size_t)u * 128 + lrowA) * FF + 2 * t;
        size_t baseB = ((size_t)u * 128 + lrowB) * FF + 2 * t;
#pragma unroll
        for (int ft = 0; ft < 16; ft++) {
            *(float2*)&d_pO[baseA + ft * 8] = make_float2(O[ft][0], O[ft][1]);
            *(float2*)&d_pO[baseB + ft * 8] = make_float2(O[ft][2], O[ft][3]);
        }
    }
}

// ---------------- combine partials + elu + L2 normalize ----------------
__global__ __launch_bounds__(128) void k_reduce() {
    int rid = blockIdx.x, cnt = d_count;
    if (rid >= cnt) return;
    int tile = rid >> 7, m = rid & 127;
    int f = threadIdx.x;
    int base = tile * JSPLIT;
    float M = -1e30f;
#pragma unroll
    for (int s = 0; s < JSPLIT; s++) M = fmaxf(M, d_pm[(base + s) * 128 + m]);
    float L = 0.f, acc = 0.f;
#pragma unroll 4
    for (int s = 0; s < JSPLIT; s++) {
        float w = __expf(d_pm[(base + s) * 128 + m] - M);
        L += w * d_pl[(base + s) * 128 + m];
        acc += w * d_pO[((size_t)(base + s) * 128 + m) * FF + f];
    }
    float v = acc / L;
    v = (v > 0.f) ? v : expm1f(v);
    __shared__ float red[4];
    float ssq = v * v;
#pragma unroll
    for (int o = 16; o; o >>= 1) ssq += __shfl_xor_sync(0xffffffffu, ssq, o);
    if ((f & 31) == 0) red[f >> 5] = ssq;
    __syncthreads();
    ssq = red[0] + red[1] + red[2] + red[3];
    float inn = 1.f / fmaxf(sqrtf(ssq), 1e-12f);
    d_Hout[(size_t)d_list[rid] * FF + f] = v * inn;
}

__global__ void k_gather(const int* __restrict__ x, float* __restrict__ out) {
    int id = blockIdx.x * blockDim.x + threadIdx.x;
    if (id < BB * 32) {
        int b = id >> 5;
        int c4 = (id & 31) * 4;
        *(float4*)&out[b * FF + c4] = *(const float4*)&d_Hout[(size_t)x[b] * FF + c4];
    }
}

extern "C" void kernel_launch(void* const* d_in, const int* in_sizes, int n_in,
                              void* d_out, int out_size) {
    const int*   x   = (const int*)d_in[0];
    const int*   adj = (const int*)d_in[1];
    const float* emb = (const float*)d_in[2];
    const float* W   = (const float*)d_in[3];
    float* out = (float*)d_out;

    cudaFuncSetAttribute(k_attn, cudaFuncAttributeMaxDynamicSharedMemorySize, SM_TOTAL);

    k_init<<<32, 256>>>();
    k_mark<<<16, 256>>>(x);
    k_compact<<<32, 256>>>();
    k_whgemm<<<256, 256>>>(emb, W);
    k_adjpack<<<4096, 256>>>(adj);
    k_imgJ<<<512, 256>>>();
    k_imgA<<<256, 256>>>();
    k_attn<<<148, 256, SM_TOTAL>>>();
    k_reduce<<<4096, 128>>>();
    k_gather<<<512, 256>>>(x, out);
}